// round 14
// baseline (speedup 1.0000x reference)
#include <cuda_runtime.h>
#include <cuda_bf16.h>
#include <cuda_fp16.h>
#include <cstddef>
#include <cstdint>

// Problem constants
#define BATCH 2
#define SEQ   2048
#define DMODEL 1024
#define NHEAD 16
#define DHEAD 64
#define MROWS (BATCH * SEQ)          // 4096
#define NQKV  (3 * NHEAD * DHEAD)    // 3072
#define OUT_ELEMS (MROWS * DMODEL)   // 4194304

// Scratch (device globals — no allocation allowed)
__device__ __align__(16) __nv_bfloat16 g_Ahi[(size_t)MROWS * DMODEL];
__device__ __align__(16) __nv_bfloat16 g_Alo[(size_t)MROWS * DMODEL];
__device__ __align__(16) __nv_bfloat16 g_Bhi[(size_t)NQKV * DMODEL];   // [N,K] transposed
__device__ __align__(16) __nv_bfloat16 g_Blo[(size_t)NQKV * DMODEL];
__device__ __align__(16) __half        g_qh [(size_t)MROWS * DMODEL];
__device__ __align__(16) __half        g_kh [(size_t)MROWS * DMODEL];
__device__ __align__(16) __half        g_vh [(size_t)MROWS * DMODEL];

// ---------------------------------------------------------------------------
// Baseline-PTX helpers (sm_103 target — NO arch-specific 'a' features)
// ---------------------------------------------------------------------------
__device__ __forceinline__ uint32_t smem_u32(const void* p) {
    uint32_t a;
    asm("{ .reg .u64 t; cvta.to.shared.u64 t, %1; cvt.u32.u64 %0, t; }"
        : "=r"(a) : "l"(p));
    return a;
}
#define CPASYNC16(dst, src) \
    asm volatile("cp.async.cg.shared.global [%0], [%1], 16;" :: "r"(dst), "l"(src))
#define CPCOMMIT() asm volatile("cp.async.commit_group;" ::: "memory")

__device__ __forceinline__ void ldx4(uint32_t* r, uint32_t addr) {
    asm volatile("ldmatrix.sync.aligned.m8n8.x4.shared.b16 {%0,%1,%2,%3}, [%4];"
                 : "=r"(r[0]), "=r"(r[1]), "=r"(r[2]), "=r"(r[3]) : "r"(addr));
}
__device__ __forceinline__ void ldx4t(uint32_t* r, uint32_t addr) {
    asm volatile("ldmatrix.sync.aligned.m8n8.x4.trans.shared.b16 {%0,%1,%2,%3}, [%4];"
                 : "=r"(r[0]), "=r"(r[1]), "=r"(r[2]), "=r"(r[3]) : "r"(addr));
}
__device__ __forceinline__ void mma_bf16(float* c, const uint32_t* a,
                                         uint32_t b0, uint32_t b1) {
    asm volatile(
        "mma.sync.aligned.m16n8k16.row.col.f32.bf16.bf16.f32 "
        "{%0,%1,%2,%3}, {%4,%5,%6,%7}, {%8,%9}, {%0,%1,%2,%3};"
        : "+f"(c[0]), "+f"(c[1]), "+f"(c[2]), "+f"(c[3])
        : "r"(a[0]), "r"(a[1]), "r"(a[2]), "r"(a[3]), "r"(b0), "r"(b1));
}
__device__ __forceinline__ void mma_f16(float* c, const uint32_t* a,
                                        uint32_t b0, uint32_t b1) {
    asm volatile(
        "mma.sync.aligned.m16n8k16.row.col.f32.f16.f16.f32 "
        "{%0,%1,%2,%3}, {%4,%5,%6,%7}, {%8,%9}, {%0,%1,%2,%3};"
        : "+f"(c[0]), "+f"(c[1]), "+f"(c[2]), "+f"(c[3])
        : "r"(a[0]), "r"(a[1]), "r"(a[2]), "r"(a[3]), "r"(b0), "r"(b1));
}
// pack two f32 into f16x2: lo half = first arg
__device__ __forceinline__ uint32_t packh2(float lo, float hi) {
    uint32_t r;
    asm("cvt.rn.f16x2.f32 %0, %1, %2;" : "=r"(r) : "f"(hi), "f"(lo));
    return r;
}
__device__ __forceinline__ __nv_bfloat162 split_hi2(float x, float y) {
    return __halves2bfloat162(__float2bfloat16(x), __float2bfloat16(y));
}
__device__ __forceinline__ __nv_bfloat162 split_lo2(float x, float y) {
    __nv_bfloat16 hx = __float2bfloat16(x), hy = __float2bfloat16(y);
    return __halves2bfloat162(__float2bfloat16(x - __bfloat162float(hx)),
                              __float2bfloat16(y - __bfloat162float(hy)));
}

// ---------------------------------------------------------------------------
// fp32 -> bf16 hi/lo split (elementwise)
// ---------------------------------------------------------------------------
__global__ void convert_hi_lo(const float* __restrict__ in,
                              __nv_bfloat16* __restrict__ hi,
                              __nv_bfloat16* __restrict__ lo, int n4)
{
    int i = blockIdx.x * blockDim.x + threadIdx.x;
    if (i >= n4) return;
    float4 v = ((const float4*)in)[i];
    __nv_bfloat162* H = (__nv_bfloat162*)hi;
    __nv_bfloat162* L = (__nv_bfloat162*)lo;
    H[2 * i]     = split_hi2(v.x, v.y);
    H[2 * i + 1] = split_hi2(v.z, v.w);
    L[2 * i]     = split_lo2(v.x, v.y);
    L[2 * i + 1] = split_lo2(v.z, v.w);
}

// W [K=1024, N] -> Wt hi/lo [N, 1024], tiled transpose + split
__global__ void convert_wt(const float* __restrict__ W,
                           __nv_bfloat16* __restrict__ hi,
                           __nv_bfloat16* __restrict__ lo, int N)
{
    __shared__ float t[32][33];
    const int nx = blockIdx.x * 32 + threadIdx.x;
    const int k0 = blockIdx.y * 32;
    #pragma unroll
    for (int j = 0; j < 4; j++)
        t[threadIdx.y + j * 8][threadIdx.x] = W[(size_t)(k0 + threadIdx.y + j * 8) * N + nx];
    __syncthreads();
    const int k = k0 + threadIdx.x;
    #pragma unroll
    for (int j = 0; j < 4; j++) {
        const int nrow = blockIdx.x * 32 + threadIdx.y + j * 8;
        float x = t[threadIdx.x][threadIdx.y + j * 8];
        __nv_bfloat16 h = __float2bfloat16(x);
        hi[(size_t)nrow * 1024 + k] = h;
        lo[(size_t)nrow * 1024 + k] = __float2bfloat16(x - __bfloat162float(h));
    }
}

// ---------------------------------------------------------------------------
// mma.sync split-bf16 GEMM: C[M,N] = A[M,1024] @ Bt[N,1024]^T + bias
// 2-stage cp.async pipeline, 2 CTAs/SM (round-11/12 winning config).
// qkv_mode (kv_out != null): emit q (x 0.125*log2e) / k / v as fp16,
// and k/v fp32 into kv_out.
// ---------------------------------------------------------------------------
#define GK       1024
#define GBK      32
#define GNC      (GK / GBK)          // 32
#define TILE_B   (128 * 80)          // 10240 B per tile
#define STAGE_B  (4 * TILE_B)        // 40960 B
#define GM_SMEM  (2 * STAGE_B)       // 81920 B  (x2 CTAs = 163840 < 228KB)

// q pre-scale: 1/sqrt(64) * log2(e)  (softmax done in base-2)
#define QSCALE   0.18033688011112042f

__global__ __launch_bounds__(256, 2)
void gemm_mma(const __nv_bfloat16* __restrict__ Ahi, const __nv_bfloat16* __restrict__ Alo,
              const __nv_bfloat16* __restrict__ Bhi, const __nv_bfloat16* __restrict__ Blo,
              const float* __restrict__ bias, float* __restrict__ C,
              int N, float* __restrict__ kv_out,
              __half* __restrict__ qh, __half* __restrict__ kh,
              __half* __restrict__ vh)
{
    extern __shared__ __align__(128) char smg[];
    const uint32_t sb = smem_u32(smg);
    const int tid = threadIdx.x, wid = tid >> 5, lane = tid & 31;
    const int wm = wid & 1, wn = wid >> 1;           // 2 x 4 warp grid
    const int bm = blockIdx.y * 128, bn = blockIdx.x * 128;

    const __nv_bfloat16* srcp[4];
    srcp[0] = Ahi + (size_t)bm * GK;
    srcp[1] = Alo + (size_t)bm * GK;
    srcp[2] = Bhi + (size_t)bn * GK;
    srcp[3] = Blo + (size_t)bn * GK;

    auto load_stage = [&](int c, int s) {
        const int k0 = c * GBK;
        #pragma unroll
        for (int t = 0; t < 4; t++) {
            const uint32_t tb = sb + s * STAGE_B + t * TILE_B;
            const __nv_bfloat16* bp = srcp[t] + k0;
            #pragma unroll
            for (int i = 0; i < 2; i++) {
                const int idx = tid + i * 256;       // 0..511
                const int row = idx >> 2, q = idx & 3;
                CPASYNC16(tb + row * 80 + q * 16,
                          (const char*)(bp + (size_t)row * GK + q * 8));
            }
        }
        CPCOMMIT();
    };

    const int a_row = (lane & 15);
    const int a_kb  = ((lane >> 4) << 3) * 2;
    const int b_row = ((lane >> 4) << 3) + (lane & 7);
    const int b_kb  = (((lane >> 3) & 1) << 3) * 2;

    float acc[4][4][4];
    #pragma unroll
    for (int i = 0; i < 4; i++)
        #pragma unroll
        for (int j = 0; j < 4; j++)
            #pragma unroll
            for (int k = 0; k < 4; k++) acc[i][j][k] = 0.f;

    load_stage(0, 0);
    #pragma unroll 1
    for (int c = 0; c < GNC; c++) {
        const int s = c & 1;
        if (c + 1 < GNC) {
            load_stage(c + 1, s ^ 1);
            asm volatile("cp.async.wait_group 1;" ::: "memory");
        } else {
            asm volatile("cp.async.wait_group 0;" ::: "memory");
        }
        __syncthreads();

        const uint32_t st = sb + s * STAGE_B;
        #pragma unroll
        for (int ks = 0; ks < 2; ks++) {
            uint32_t ah[4][4], al[4][4], bh[2][4], bl[2][4];
            const uint32_t akb = ks * 32 + a_kb;
            const uint32_t bkb = ks * 32 + b_kb;
            #pragma unroll
            for (int mf = 0; mf < 4; mf++) {
                const uint32_t off = (uint32_t)(wm * 64 + mf * 16 + a_row) * 80 + akb;
                ldx4(ah[mf], st + 0 * TILE_B + off);
                ldx4(al[mf], st + 1 * TILE_B + off);
            }
            #pragma unroll
            for (int nf2 = 0; nf2 < 2; nf2++) {
                const uint32_t off = (uint32_t)(wn * 32 + nf2 * 16 + b_row) * 80 + bkb;
                ldx4(bh[nf2], st + 2 * TILE_B + off);
                ldx4(bl[nf2], st + 3 * TILE_B + off);
            }
            #pragma unroll
            for (int mf = 0; mf < 4; mf++)
                #pragma unroll
                for (int nf2 = 0; nf2 < 2; nf2++)
                    #pragma unroll
                    for (int j = 0; j < 2; j++) {
                        float* a4 = acc[mf][nf2 * 2 + j];
                        mma_bf16(a4, ah[mf], bh[nf2][2 * j], bh[nf2][2 * j + 1]);
                        mma_bf16(a4, al[mf], bh[nf2][2 * j], bh[nf2][2 * j + 1]);
                        mma_bf16(a4, ah[mf], bl[nf2][2 * j], bl[nf2][2 * j + 1]);
                    }
        }
        __syncthreads();
    }

    // Epilogue
    const int gid = lane >> 2, tig = lane & 3;
    #pragma unroll
    for (int mf = 0; mf < 4; mf++) {
        #pragma unroll
        for (int nf = 0; nf < 4; nf++) {
            const int n = bn + wn * 32 + nf * 8 + 2 * tig;
            const float bx = bias[n], by = bias[n + 1];
            #pragma unroll
            for (int h = 0; h < 2; h++) {
                const int row = bm + wm * 64 + mf * 16 + gid + h * 8;
                float2 cv;
                cv.x = acc[mf][nf][2 * h + 0] + bx;
                cv.y = acc[mf][nf][2 * h + 1] + by;
                if (!kv_out) {
                    *(float2*)&C[(size_t)row * N + n] = cv;
                } else if (n < 1024) {               // q: scale (incl. log2e), fp16
                    *(__half2*)&qh[(size_t)row * DMODEL + n] =
                        __floats2half2_rn(cv.x * QSCALE, cv.y * QSCALE);
                } else if (n < 2048) {               // k: fp16 + fp32 out
                    const int nk = n - 1024;
                    *(__half2*)&kh[(size_t)row * DMODEL + nk] = __floats2half2_rn(cv.x, cv.y);
                    *(float2*)&kv_out[(size_t)row * DMODEL + nk] = cv;
                } else {                             // v: fp16 + fp32 out
                    const int nv = n - 2048;
                    *(__half2*)&vh[(size_t)row * DMODEL + nv] = __floats2half2_rn(cv.x, cv.y);
                    *(float2*)&kv_out[(size_t)OUT_ELEMS + (size_t)row * DMODEL + nv] = cv;
                }
            }
        }
    }
}

// ---------------------------------------------------------------------------
// Causal flash attention on mma.sync, all-fp16 operands, base-2 softmax
// (q pre-scaled by log2e; exp2f everywhere — softmax-invariant).
// CTA: 128 q-rows x (64-token kv tiles), 8 warps each own m16, full n width.
// ---------------------------------------------------------------------------
#define FQ0    0
#define FSTG   (128 * 144)           // 18432
#define FKH    0
#define FV     9216
#define FSTGB  18432
#define FL_SMEM (FSTG + 2 * FSTGB)   // 55296  (x2 CTAs = 110592 < 228KB)

__global__ __launch_bounds__(256, 2)
void flash_mma(const __half* __restrict__ qh, const __half* __restrict__ kh,
               const __half* __restrict__ vh,
               __nv_bfloat16* __restrict__ ohi, __nv_bfloat16* __restrict__ olo)
{
    extern __shared__ __align__(128) char smf[];
    const uint32_t sb = smem_u32(smf);
    const int tid = threadIdx.x, wid = tid >> 5, lane = tid & 31;
    const int qt = (int)gridDim.x - 1 - (int)blockIdx.x;   // long blocks first
    const int h = blockIdx.y, b = blockIdx.z;
    const int bq0 = qt * 128;
    const int nkv = 2 * (qt + 1);
    const size_t tokbase = (size_t)b * SEQ;
    const int hoff = h * DHEAD;

    // Q tile -> smem (128 rows x 64 f16, row stride 144 B)
    #pragma unroll
    for (int i = 0; i < 4; i++) {
        const int idx = tid + 256 * i;                 // 0..1023
        const int row = idx >> 3, q = idx & 7;
        const size_t g = (tokbase + bq0 + row) * DMODEL + hoff + q * 8;
        CPASYNC16(sb + FQ0 + row * 144 + q * 16, (const char*)(qh + g));
    }

    auto load_kv = [&](int c, int s) {
        const size_t rb = tokbase + c * 64;
        const uint32_t st = sb + FSTG + s * FSTGB;
        #pragma unroll
        for (int i = 0; i < 2; i++) {
            const int idx = tid + 256 * i;             // 0..511
            const int row = idx >> 3, q = idx & 7;
            const size_t g = (rb + row) * DMODEL + hoff + q * 8;
            CPASYNC16(st + FKH + row * 144 + q * 16, (const char*)(kh + g));
            CPASYNC16(st + FV  + row * 144 + q * 16, (const char*)(vh + g));
        }
        CPCOMMIT();
    };
    load_kv(0, 0);   // group 0 = Q + kv stage 0

    const int a_row = (lane & 15);
    const int a_kb  = ((lane >> 4) << 3) * 2;
    const int b_row = ((lane >> 4) << 3) + (lane & 7);
    const int b_kb  = (((lane >> 3) & 1) << 3) * 2;
    const int gid = lane >> 2, tig = lane & 3;

    const int wrow0 = bq0 + wid * 16;                  // warp min row
    const int r0 = wrow0 + gid, r1 = r0 + 8;           // this lane's rows

    uint32_t qh_[4][4];
    float o_[8][4];
    #pragma unroll
    for (int i = 0; i < 8; i++)
        #pragma unroll
        for (int j = 0; j < 4; j++) o_[i][j] = 0.f;
    float m0 = -1e30f, m1 = -1e30f, l0 = 0.f, l1 = 0.f;
    bool qloaded = false;

    #pragma unroll 1
    for (int c = 0; c < nkv; c++) {
        const int s = c & 1;
        if (c + 1 < nkv) {
            load_kv(c + 1, s ^ 1);
            asm volatile("cp.async.wait_group 1;" ::: "memory");
        } else {
            asm volatile("cp.async.wait_group 0;" ::: "memory");
        }
        __syncthreads();

        if (!qloaded) {
            qloaded = true;
            const uint32_t off = (uint32_t)(wid * 16 + a_row) * 144 + a_kb;
            #pragma unroll
            for (int kf = 0; kf < 4; kf++)
                ldx4(qh_[kf], sb + FQ0 + off + kf * 32);
        }

        const int kv0 = c * 64;
        if (kv0 <= wrow0 + 15) {                       // not fully masked for warp
            const uint32_t st = sb + FSTG + s * FSTGB;

            // S' = Q K^T (base-2 logits; single f16 product)
            float s_[8][4];
            #pragma unroll
            for (int i = 0; i < 8; i++)
                #pragma unroll
                for (int j = 0; j < 4; j++) s_[i][j] = 0.f;
            #pragma unroll
            for (int kf = 0; kf < 4; kf++) {
                #pragma unroll
                for (int nf2 = 0; nf2 < 4; nf2++) {
                    uint32_t bh[4];
                    const uint32_t off = (uint32_t)(nf2 * 16 + b_row) * 144 + b_kb + kf * 32;
                    ldx4(bh, st + FKH + off);
                    mma_f16(s_[nf2 * 2],     qh_[kf], bh[0], bh[1]);
                    mma_f16(s_[nf2 * 2 + 1], qh_[kf], bh[2], bh[3]);
                }
            }

            // causal mask (only near the diagonal)
            if (kv0 + 63 > wrow0) {
                #pragma unroll
                for (int nf = 0; nf < 8; nf++)
                    #pragma unroll
                    for (int e = 0; e < 2; e++) {
                        const int col = kv0 + 8 * nf + 2 * tig + e;
                        if (col > r0) s_[nf][e]     = -1e30f;
                        if (col > r1) s_[nf][2 + e] = -1e30f;
                    }
            }

            // online softmax in base-2 (quad-lane reductions)
            float mx0 = -1e30f, mx1 = -1e30f;
            #pragma unroll
            for (int nf = 0; nf < 8; nf++) {
                mx0 = fmaxf(mx0, fmaxf(s_[nf][0], s_[nf][1]));
                mx1 = fmaxf(mx1, fmaxf(s_[nf][2], s_[nf][3]));
            }
            mx0 = fmaxf(mx0, __shfl_xor_sync(0xffffffffu, mx0, 1));
            mx0 = fmaxf(mx0, __shfl_xor_sync(0xffffffffu, mx0, 2));
            mx1 = fmaxf(mx1, __shfl_xor_sync(0xffffffffu, mx1, 1));
            mx1 = fmaxf(mx1, __shfl_xor_sync(0xffffffffu, mx1, 2));
            const float mn0 = fmaxf(m0, mx0), mn1 = fmaxf(m1, mx1);
            const float sc0 = exp2f(m0 - mn0), sc1 = exp2f(m1 - mn1);
            float rs0 = 0.f, rs1 = 0.f;
            #pragma unroll
            for (int nf = 0; nf < 8; nf++) {
                s_[nf][0] = exp2f(s_[nf][0] - mn0); rs0 += s_[nf][0];
                s_[nf][1] = exp2f(s_[nf][1] - mn0); rs0 += s_[nf][1];
                s_[nf][2] = exp2f(s_[nf][2] - mn1); rs1 += s_[nf][2];
                s_[nf][3] = exp2f(s_[nf][3] - mn1); rs1 += s_[nf][3];
            }
            rs0 += __shfl_xor_sync(0xffffffffu, rs0, 1);
            rs0 += __shfl_xor_sync(0xffffffffu, rs0, 2);
            rs1 += __shfl_xor_sync(0xffffffffu, rs1, 1);
            rs1 += __shfl_xor_sync(0xffffffffu, rs1, 2);
            l0 = l0 * sc0 + rs0; m0 = mn0;
            l1 = l1 * sc1 + rs1; m1 = mn1;
            #pragma unroll
            for (int nf = 0; nf < 8; nf++) {
                o_[nf][0] *= sc0; o_[nf][1] *= sc0;
                o_[nf][2] *= sc1; o_[nf][3] *= sc1;
            }

            // O += P V  (P from regs, V^T via ldmatrix.trans)
            #pragma unroll
            for (int kg = 0; kg < 4; kg++) {
                uint32_t pa[4];
                pa[0] = packh2(s_[2 * kg][0],     s_[2 * kg][1]);
                pa[1] = packh2(s_[2 * kg][2],     s_[2 * kg][3]);
                pa[2] = packh2(s_[2 * kg + 1][0], s_[2 * kg + 1][1]);
                pa[3] = packh2(s_[2 * kg + 1][2], s_[2 * kg + 1][3]);
                #pragma unroll
                for (int nf2 = 0; nf2 < 4; nf2++) {
                    uint32_t bv[4];
                    const uint32_t voff = (uint32_t)(kg * 16 + (lane & 15)) * 144
                                        + (uint32_t)(nf2 * 16 + (lane >> 4) * 8) * 2;
                    ldx4t(bv, st + FV + voff);
                    mma_f16(o_[nf2 * 2],     pa, bv[0], bv[1]);
                    mma_f16(o_[nf2 * 2 + 1], pa, bv[2], bv[3]);
                }
            }
        }
        __syncthreads();
    }

    // normalize + store as bf16 hi/lo split (input for out-proj GEMM)
    const float inv0 = 1.0f / l0, inv1 = 1.0f / l1;
    #pragma unroll
    for (int nf = 0; nf < 8; nf++) {
        const int n = hoff + 8 * nf + 2 * tig;
        const float x0 = o_[nf][0] * inv0, y0 = o_[nf][1] * inv0;
        const float x1 = o_[nf][2] * inv1, y1 = o_[nf][3] * inv1;
        const size_t g0 = (tokbase + r0) * DMODEL + n;
        const size_t g1 = (tokbase + r1) * DMODEL + n;
        *(__nv_bfloat162*)&ohi[g0] = split_hi2(x0, y0);
        *(__nv_bfloat162*)&olo[g0] = split_lo2(x0, y0);
        *(__nv_bfloat162*)&ohi[g1] = split_hi2(x1, y1);
        *(__nv_bfloat162*)&olo[g1] = split_lo2(x1, y1);
    }
}

// ---------------------------------------------------------------------------
extern "C" void kernel_launch(void* const* d_in, const int* in_sizes, int n_in,
                              void* d_out, int out_size)
{
    const float* input = (const float*)d_in[0];
    // d_in[1] = mask (causal, hardcoded — ignored)
    const float* W_qkv = (const float*)d_in[2];
    const float* b_qkv = (const float*)d_in[3];
    const float* W_out = (const float*)d_in[4];
    const float* b_out = (const float*)d_in[5];
    float* out = (float*)d_out;

    __nv_bfloat16 *ahi, *alo, *bhi, *blo;
    __half *qh, *kh, *vh;
    cudaGetSymbolAddress((void**)&ahi, g_Ahi);
    cudaGetSymbolAddress((void**)&alo, g_Alo);
    cudaGetSymbolAddress((void**)&bhi, g_Bhi);
    cudaGetSymbolAddress((void**)&blo, g_Blo);
    cudaGetSymbolAddress((void**)&qh,  g_qh);
    cudaGetSymbolAddress((void**)&kh,  g_kh);
    cudaGetSymbolAddress((void**)&vh,  g_vh);

    float* kv_out = out + OUT_ELEMS;   // (out, k, v) layout

    cudaFuncSetAttribute(gemm_mma, cudaFuncAttributeMaxDynamicSharedMemorySize, GM_SMEM);
    cudaFuncSetAttribute(flash_mma, cudaFuncAttributeMaxDynamicSharedMemorySize, FL_SMEM);

    // 1) split input + W_qkv^T to bf16 hi/lo
    convert_hi_lo<<<(OUT_ELEMS / 4 + 255) / 256, 256>>>(input, ahi, alo, OUT_ELEMS / 4);
    convert_wt<<<dim3(NQKV / 32, DMODEL / 32), dim3(32, 8)>>>(W_qkv, bhi, blo, NQKV);

    // 2) QKV gemm -> q/k/v fp16, k/v fp32 to output
    gemm_mma<<<dim3(NQKV / 128, MROWS / 128), 256, GM_SMEM>>>(
        ahi, alo, bhi, blo, b_qkv, nullptr, NQKV, kv_out, qh, kh, vh);

    // 3) causal flash attention (tensor cores); writes att hi/lo in place of A
    flash_mma<<<dim3(SEQ / 128, NHEAD, BATCH), 256, FL_SMEM>>>(
        qh, kh, vh, ahi, alo);

    // 4) out = att @ W_out + b_out
    convert_wt<<<dim3(DMODEL / 32, DMODEL / 32), dim3(32, 8)>>>(W_out, bhi, blo, DMODEL);
    gemm_mma<<<dim3(DMODEL / 128, MROWS / 128), 256, GM_SMEM>>>(
        ahi, alo, bhi, blo, b_out, out, DMODEL, nullptr,
        nullptr, nullptr, nullptr);
}

// round 15
// speedup vs baseline: 1.5557x; 1.5557x over previous
#include <cuda_runtime.h>
#include <cuda_bf16.h>
#include <cuda_fp16.h>
#include <cstddef>
#include <cstdint>

// Problem constants
#define BATCH 2
#define SEQ   2048
#define DMODEL 1024
#define NHEAD 16
#define DHEAD 64
#define MROWS (BATCH * SEQ)          // 4096
#define NQKV  (3 * NHEAD * DHEAD)    // 3072
#define OUT_ELEMS (MROWS * DMODEL)   // 4194304

// Scratch (device globals — no allocation allowed)
__device__ __align__(16) __nv_bfloat16 g_Ahi[(size_t)MROWS * DMODEL];
__device__ __align__(16) __nv_bfloat16 g_Alo[(size_t)MROWS * DMODEL];
__device__ __align__(16) __nv_bfloat16 g_Bhi[(size_t)NQKV * DMODEL];   // [N,K] transposed
__device__ __align__(16) __nv_bfloat16 g_Blo[(size_t)NQKV * DMODEL];
__device__ __align__(16) __half        g_qh [(size_t)MROWS * DMODEL];
__device__ __align__(16) __half        g_kh [(size_t)MROWS * DMODEL];
__device__ __align__(16) __half        g_vh [(size_t)MROWS * DMODEL];

// ---------------------------------------------------------------------------
// Baseline-PTX helpers (sm_103 target — NO arch-specific 'a' features)
// ---------------------------------------------------------------------------
__device__ __forceinline__ uint32_t smem_u32(const void* p) {
    uint32_t a;
    asm("{ .reg .u64 t; cvta.to.shared.u64 t, %1; cvt.u32.u64 %0, t; }"
        : "=r"(a) : "l"(p));
    return a;
}
#define CPASYNC16(dst, src) \
    asm volatile("cp.async.cg.shared.global [%0], [%1], 16;" :: "r"(dst), "l"(src))
#define CPCOMMIT() asm volatile("cp.async.commit_group;" ::: "memory")

__device__ __forceinline__ void ldx4(uint32_t* r, uint32_t addr) {
    asm volatile("ldmatrix.sync.aligned.m8n8.x4.shared.b16 {%0,%1,%2,%3}, [%4];"
                 : "=r"(r[0]), "=r"(r[1]), "=r"(r[2]), "=r"(r[3]) : "r"(addr));
}
__device__ __forceinline__ void ldx4t(uint32_t* r, uint32_t addr) {
    asm volatile("ldmatrix.sync.aligned.m8n8.x4.trans.shared.b16 {%0,%1,%2,%3}, [%4];"
                 : "=r"(r[0]), "=r"(r[1]), "=r"(r[2]), "=r"(r[3]) : "r"(addr));
}
__device__ __forceinline__ void mma_bf16(float* c, const uint32_t* a,
                                         uint32_t b0, uint32_t b1) {
    asm volatile(
        "mma.sync.aligned.m16n8k16.row.col.f32.bf16.bf16.f32 "
        "{%0,%1,%2,%3}, {%4,%5,%6,%7}, {%8,%9}, {%0,%1,%2,%3};"
        : "+f"(c[0]), "+f"(c[1]), "+f"(c[2]), "+f"(c[3])
        : "r"(a[0]), "r"(a[1]), "r"(a[2]), "r"(a[3]), "r"(b0), "r"(b1));
}
__device__ __forceinline__ void mma_f16(float* c, const uint32_t* a,
                                        uint32_t b0, uint32_t b1) {
    asm volatile(
        "mma.sync.aligned.m16n8k16.row.col.f32.f16.f16.f32 "
        "{%0,%1,%2,%3}, {%4,%5,%6,%7}, {%8,%9}, {%0,%1,%2,%3};"
        : "+f"(c[0]), "+f"(c[1]), "+f"(c[2]), "+f"(c[3])
        : "r"(a[0]), "r"(a[1]), "r"(a[2]), "r"(a[3]), "r"(b0), "r"(b1));
}
// pack two f32 into f16x2: lo half = first arg
__device__ __forceinline__ uint32_t packh2(float lo, float hi) {
    uint32_t r;
    asm("cvt.rn.f16x2.f32 %0, %1, %2;" : "=r"(r) : "f"(hi), "f"(lo));
    return r;
}
__device__ __forceinline__ __nv_bfloat162 split_hi2(float x, float y) {
    return __halves2bfloat162(__float2bfloat16(x), __float2bfloat16(y));
}
__device__ __forceinline__ __nv_bfloat162 split_lo2(float x, float y) {
    __nv_bfloat16 hx = __float2bfloat16(x), hy = __float2bfloat16(y);
    return __halves2bfloat162(__float2bfloat16(x - __bfloat162float(hx)),
                              __float2bfloat16(y - __bfloat162float(hy)));
}

// ---------------------------------------------------------------------------
// fp32 -> bf16 hi/lo split (elementwise)
// ---------------------------------------------------------------------------
__global__ void convert_hi_lo(const float* __restrict__ in,
                              __nv_bfloat16* __restrict__ hi,
                              __nv_bfloat16* __restrict__ lo, int n4)
{
    int i = blockIdx.x * blockDim.x + threadIdx.x;
    if (i >= n4) return;
    float4 v = ((const float4*)in)[i];
    __nv_bfloat162* H = (__nv_bfloat162*)hi;
    __nv_bfloat162* L = (__nv_bfloat162*)lo;
    H[2 * i]     = split_hi2(v.x, v.y);
    H[2 * i + 1] = split_hi2(v.z, v.w);
    L[2 * i]     = split_lo2(v.x, v.y);
    L[2 * i + 1] = split_lo2(v.z, v.w);
}

// W [K=1024, N] -> Wt hi/lo [N, 1024], tiled transpose + split
__global__ void convert_wt(const float* __restrict__ W,
                           __nv_bfloat16* __restrict__ hi,
                           __nv_bfloat16* __restrict__ lo, int N)
{
    __shared__ float t[32][33];
    const int nx = blockIdx.x * 32 + threadIdx.x;
    const int k0 = blockIdx.y * 32;
    #pragma unroll
    for (int j = 0; j < 4; j++)
        t[threadIdx.y + j * 8][threadIdx.x] = W[(size_t)(k0 + threadIdx.y + j * 8) * N + nx];
    __syncthreads();
    const int k = k0 + threadIdx.x;
    #pragma unroll
    for (int j = 0; j < 4; j++) {
        const int nrow = blockIdx.x * 32 + threadIdx.y + j * 8;
        float x = t[threadIdx.x][threadIdx.y + j * 8];
        __nv_bfloat16 h = __float2bfloat16(x);
        hi[(size_t)nrow * 1024 + k] = h;
        lo[(size_t)nrow * 1024 + k] = __float2bfloat16(x - __bfloat162float(h));
    }
}

// ---------------------------------------------------------------------------
// mma.sync split-bf16 GEMM: C[M,N] = A[M,1024] @ Bt[N,1024]^T + bias
// 2-stage cp.async pipeline, 2 CTAs/SM (round-11/12 winning config).
// qkv_mode (kv_out != null): emit q (x 0.125*log2e) / k / v as fp16,
// and k/v fp32 into kv_out.
// ---------------------------------------------------------------------------
#define GK       1024
#define GBK      32
#define GNC      (GK / GBK)          // 32
#define TILE_B   (128 * 80)          // 10240 B per tile
#define STAGE_B  (4 * TILE_B)        // 40960 B
#define GM_SMEM  (2 * STAGE_B)       // 81920 B  (x2 CTAs = 163840 < 228KB)

// q pre-scale: 1/sqrt(64) * log2(e)  (softmax done in base-2)
#define QSCALE   0.18033688011112042f

__global__ __launch_bounds__(256, 2)
void gemm_mma(const __nv_bfloat16* __restrict__ Ahi, const __nv_bfloat16* __restrict__ Alo,
              const __nv_bfloat16* __restrict__ Bhi, const __nv_bfloat16* __restrict__ Blo,
              const float* __restrict__ bias, float* __restrict__ C,
              int N, float* __restrict__ kv_out,
              __half* __restrict__ qh, __half* __restrict__ kh,
              __half* __restrict__ vh)
{
    extern __shared__ __align__(128) char smg[];
    const uint32_t sb = smem_u32(smg);
    const int tid = threadIdx.x, wid = tid >> 5, lane = tid & 31;
    const int wm = wid & 1, wn = wid >> 1;           // 2 x 4 warp grid
    const int bm = blockIdx.y * 128, bn = blockIdx.x * 128;

    const __nv_bfloat16* srcp[4];
    srcp[0] = Ahi + (size_t)bm * GK;
    srcp[1] = Alo + (size_t)bm * GK;
    srcp[2] = Bhi + (size_t)bn * GK;
    srcp[3] = Blo + (size_t)bn * GK;

    auto load_stage = [&](int c, int s) {
        const int k0 = c * GBK;
        #pragma unroll
        for (int t = 0; t < 4; t++) {
            const uint32_t tb = sb + s * STAGE_B + t * TILE_B;
            const __nv_bfloat16* bp = srcp[t] + k0;
            #pragma unroll
            for (int i = 0; i < 2; i++) {
                const int idx = tid + i * 256;       // 0..511
                const int row = idx >> 2, q = idx & 3;
                CPASYNC16(tb + row * 80 + q * 16,
                          (const char*)(bp + (size_t)row * GK + q * 8));
            }
        }
        CPCOMMIT();
    };

    const int a_row = (lane & 15);
    const int a_kb  = ((lane >> 4) << 3) * 2;
    const int b_row = ((lane >> 4) << 3) + (lane & 7);
    const int b_kb  = (((lane >> 3) & 1) << 3) * 2;

    float acc[4][4][4];
    #pragma unroll
    for (int i = 0; i < 4; i++)
        #pragma unroll
        for (int j = 0; j < 4; j++)
            #pragma unroll
            for (int k = 0; k < 4; k++) acc[i][j][k] = 0.f;

    load_stage(0, 0);
    #pragma unroll 1
    for (int c = 0; c < GNC; c++) {
        const int s = c & 1;
        if (c + 1 < GNC) {
            load_stage(c + 1, s ^ 1);
            asm volatile("cp.async.wait_group 1;" ::: "memory");
        } else {
            asm volatile("cp.async.wait_group 0;" ::: "memory");
        }
        __syncthreads();

        const uint32_t st = sb + s * STAGE_B;
        #pragma unroll
        for (int ks = 0; ks < 2; ks++) {
            uint32_t ah[4][4], al[4][4], bh[2][4], bl[2][4];
            const uint32_t akb = ks * 32 + a_kb;
            const uint32_t bkb = ks * 32 + b_kb;
            #pragma unroll
            for (int mf = 0; mf < 4; mf++) {
                const uint32_t off = (uint32_t)(wm * 64 + mf * 16 + a_row) * 80 + akb;
                ldx4(ah[mf], st + 0 * TILE_B + off);
                ldx4(al[mf], st + 1 * TILE_B + off);
            }
            #pragma unroll
            for (int nf2 = 0; nf2 < 2; nf2++) {
                const uint32_t off = (uint32_t)(wn * 32 + nf2 * 16 + b_row) * 80 + bkb;
                ldx4(bh[nf2], st + 2 * TILE_B + off);
                ldx4(bl[nf2], st + 3 * TILE_B + off);
            }
            #pragma unroll
            for (int mf = 0; mf < 4; mf++)
                #pragma unroll
                for (int nf2 = 0; nf2 < 2; nf2++)
                    #pragma unroll
                    for (int j = 0; j < 2; j++) {
                        float* a4 = acc[mf][nf2 * 2 + j];
                        mma_bf16(a4, ah[mf], bh[nf2][2 * j], bh[nf2][2 * j + 1]);
                        mma_bf16(a4, al[mf], bh[nf2][2 * j], bh[nf2][2 * j + 1]);
                        mma_bf16(a4, ah[mf], bl[nf2][2 * j], bl[nf2][2 * j + 1]);
                    }
        }
        __syncthreads();
    }

    // Epilogue
    const int gid = lane >> 2, tig = lane & 3;
    #pragma unroll
    for (int mf = 0; mf < 4; mf++) {
        #pragma unroll
        for (int nf = 0; nf < 4; nf++) {
            const int n = bn + wn * 32 + nf * 8 + 2 * tig;
            const float bx = bias[n], by = bias[n + 1];
            #pragma unroll
            for (int h = 0; h < 2; h++) {
                const int row = bm + wm * 64 + mf * 16 + gid + h * 8;
                float2 cv;
                cv.x = acc[mf][nf][2 * h + 0] + bx;
                cv.y = acc[mf][nf][2 * h + 1] + by;
                if (!kv_out) {
                    *(float2*)&C[(size_t)row * N + n] = cv;
                } else if (n < 1024) {               // q: scale (incl. log2e), fp16
                    *(__half2*)&qh[(size_t)row * DMODEL + n] =
                        __floats2half2_rn(cv.x * QSCALE, cv.y * QSCALE);
                } else if (n < 2048) {               // k: fp16 + fp32 out
                    const int nk = n - 1024;
                    *(__half2*)&kh[(size_t)row * DMODEL + nk] = __floats2half2_rn(cv.x, cv.y);
                    *(float2*)&kv_out[(size_t)row * DMODEL + nk] = cv;
                } else {                             // v: fp16 + fp32 out
                    const int nv = n - 2048;
                    *(__half2*)&vh[(size_t)row * DMODEL + nv] = __floats2half2_rn(cv.x, cv.y);
                    *(float2*)&kv_out[(size_t)OUT_ELEMS + (size_t)row * DMODEL + nv] = cv;
                }
            }
        }
    }
}

// ---------------------------------------------------------------------------
// Causal flash attention on mma.sync, all-fp16 operands, base-2 softmax
// (q pre-scaled by log2e; exp2f everywhere — softmax-invariant).
// CTA: 128 q-rows x (64-token kv tiles), 8 warps each own m16, full n width.
// ---------------------------------------------------------------------------
#define FQ0    0
#define FSTG   (128 * 144)           // 18432
#define FKH    0
#define FV     9216
#define FSTGB  18432
#define FL_SMEM (FSTG + 2 * FSTGB)   // 55296  (x2 CTAs = 110592 < 228KB)

__global__ __launch_bounds__(256, 2)
void flash_mma(const __half* __restrict__ qh, const __half* __restrict__ kh,
               const __half* __restrict__ vh,
               __nv_bfloat16* __restrict__ ohi, __nv_bfloat16* __restrict__ olo)
{
    extern __shared__ __align__(128) char smf[];
    const uint32_t sb = smem_u32(smf);
    const int tid = threadIdx.x, wid = tid >> 5, lane = tid & 31;
    const int qt = (int)gridDim.x - 1 - (int)blockIdx.x;   // long blocks first
    const int h = blockIdx.y, b = blockIdx.z;
    const int bq0 = qt * 128;
    const int nkv = 2 * (qt + 1);
    const size_t tokbase = (size_t)b * SEQ;
    const int hoff = h * DHEAD;

    // Q tile -> smem (128 rows x 64 f16, row stride 144 B)
    #pragma unroll
    for (int i = 0; i < 4; i++) {
        const int idx = tid + 256 * i;                 // 0..1023
        const int row = idx >> 3, q = idx & 7;
        const size_t g = (tokbase + bq0 + row) * DMODEL + hoff + q * 8;
        CPASYNC16(sb + FQ0 + row * 144 + q * 16, (const char*)(qh + g));
    }

    auto load_kv = [&](int c, int s) {
        const size_t rb = tokbase + c * 64;
        const uint32_t st = sb + FSTG + s * FSTGB;
        #pragma unroll
        for (int i = 0; i < 2; i++) {
            const int idx = tid + 256 * i;             // 0..511
            const int row = idx >> 3, q = idx & 7;
            const size_t g = (rb + row) * DMODEL + hoff + q * 8;
            CPASYNC16(st + FKH + row * 144 + q * 16, (const char*)(kh + g));
            CPASYNC16(st + FV  + row * 144 + q * 16, (const char*)(vh + g));
        }
        CPCOMMIT();
    };
    load_kv(0, 0);   // group 0 = Q + kv stage 0

    const int a_row = (lane & 15);
    const int a_kb  = ((lane >> 4) << 3) * 2;
    const int b_row = ((lane >> 4) << 3) + (lane & 7);
    const int b_kb  = (((lane >> 3) & 1) << 3) * 2;
    const int gid = lane >> 2, tig = lane & 3;

    const int wrow0 = bq0 + wid * 16;                  // warp min row
    const int r0 = wrow0 + gid, r1 = r0 + 8;           // this lane's rows

    uint32_t qh_[4][4];
    float o_[8][4];
    #pragma unroll
    for (int i = 0; i < 8; i++)
        #pragma unroll
        for (int j = 0; j < 4; j++) o_[i][j] = 0.f;
    float m0 = -1e30f, m1 = -1e30f, l0 = 0.f, l1 = 0.f;
    bool qloaded = false;

    #pragma unroll 1
    for (int c = 0; c < nkv; c++) {
        const int s = c & 1;
        if (c + 1 < nkv) {
            load_kv(c + 1, s ^ 1);
            asm volatile("cp.async.wait_group 1;" ::: "memory");
        } else {
            asm volatile("cp.async.wait_group 0;" ::: "memory");
        }
        __syncthreads();

        if (!qloaded) {
            qloaded = true;
            const uint32_t off = (uint32_t)(wid * 16 + a_row) * 144 + a_kb;
            #pragma unroll
            for (int kf = 0; kf < 4; kf++)
                ldx4(qh_[kf], sb + FQ0 + off + kf * 32);
        }

        const int kv0 = c * 64;
        if (kv0 <= wrow0 + 15) {                       // not fully masked for warp
            const uint32_t st = sb + FSTG + s * FSTGB;

            // S' = Q K^T (base-2 logits; single f16 product)
            float s_[8][4];
            #pragma unroll
            for (int i = 0; i < 8; i++)
                #pragma unroll
                for (int j = 0; j < 4; j++) s_[i][j] = 0.f;
            #pragma unroll
            for (int kf = 0; kf < 4; kf++) {
                #pragma unroll
                for (int nf2 = 0; nf2 < 4; nf2++) {
                    uint32_t bh[4];
                    const uint32_t off = (uint32_t)(nf2 * 16 + b_row) * 144 + b_kb + kf * 32;
                    ldx4(bh, st + FKH + off);
                    mma_f16(s_[nf2 * 2],     qh_[kf], bh[0], bh[1]);
                    mma_f16(s_[nf2 * 2 + 1], qh_[kf], bh[2], bh[3]);
                }
            }

            // causal mask (only near the diagonal)
            if (kv0 + 63 > wrow0) {
                #pragma unroll
                for (int nf = 0; nf < 8; nf++)
                    #pragma unroll
                    for (int e = 0; e < 2; e++) {
                        const int col = kv0 + 8 * nf + 2 * tig + e;
                        if (col > r0) s_[nf][e]     = -1e30f;
                        if (col > r1) s_[nf][2 + e] = -1e30f;
                    }
            }

            // online softmax in base-2 (quad-lane reductions)
            float mx0 = -1e30f, mx1 = -1e30f;
            #pragma unroll
            for (int nf = 0; nf < 8; nf++) {
                mx0 = fmaxf(mx0, fmaxf(s_[nf][0], s_[nf][1]));
                mx1 = fmaxf(mx1, fmaxf(s_[nf][2], s_[nf][3]));
            }
            mx0 = fmaxf(mx0, __shfl_xor_sync(0xffffffffu, mx0, 1));
            mx0 = fmaxf(mx0, __shfl_xor_sync(0xffffffffu, mx0, 2));
            mx1 = fmaxf(mx1, __shfl_xor_sync(0xffffffffu, mx1, 1));
            mx1 = fmaxf(mx1, __shfl_xor_sync(0xffffffffu, mx1, 2));
            const float mn0 = fmaxf(m0, mx0), mn1 = fmaxf(m1, mx1);
            const float sc0 = exp2f(m0 - mn0), sc1 = exp2f(m1 - mn1);
            float rs0 = 0.f, rs1 = 0.f;
            #pragma unroll
            for (int nf = 0; nf < 8; nf++) {
                s_[nf][0] = exp2f(s_[nf][0] - mn0); rs0 += s_[nf][0];
                s_[nf][1] = exp2f(s_[nf][1] - mn0); rs0 += s_[nf][1];
                s_[nf][2] = exp2f(s_[nf][2] - mn1); rs1 += s_[nf][2];
                s_[nf][3] = exp2f(s_[nf][3] - mn1); rs1 += s_[nf][3];
            }
            rs0 += __shfl_xor_sync(0xffffffffu, rs0, 1);
            rs0 += __shfl_xor_sync(0xffffffffu, rs0, 2);
            rs1 += __shfl_xor_sync(0xffffffffu, rs1, 1);
            rs1 += __shfl_xor_sync(0xffffffffu, rs1, 2);
            l0 = l0 * sc0 + rs0; m0 = mn0;
            l1 = l1 * sc1 + rs1; m1 = mn1;
            #pragma unroll
            for (int nf = 0; nf < 8; nf++) {
                o_[nf][0] *= sc0; o_[nf][1] *= sc0;
                o_[nf][2] *= sc1; o_[nf][3] *= sc1;
            }

            // O += P V  (P from regs, V^T via ldmatrix.trans)
            #pragma unroll
            for (int kg = 0; kg < 4; kg++) {
                uint32_t pa[4];
                pa[0] = packh2(s_[2 * kg][0],     s_[2 * kg][1]);
                pa[1] = packh2(s_[2 * kg][2],     s_[2 * kg][3]);
                pa[2] = packh2(s_[2 * kg + 1][0], s_[2 * kg + 1][1]);
                pa[3] = packh2(s_[2 * kg + 1][2], s_[2 * kg + 1][3]);
                #pragma unroll
                for (int nf2 = 0; nf2 < 4; nf2++) {
                    uint32_t bv[4];
                    const uint32_t voff = (uint32_t)(kg * 16 + (lane & 15)) * 144
                                        + (uint32_t)(nf2 * 16 + (lane >> 4) * 8) * 2;
                    ldx4t(bv, st + FV + voff);
                    mma_f16(o_[nf2 * 2],     pa, bv[0], bv[1]);
                    mma_f16(o_[nf2 * 2 + 1], pa, bv[2], bv[3]);
                }
            }
        }
        __syncthreads();
    }

    // normalize + store as bf16 hi/lo split (input for out-proj GEMM)
    const float inv0 = 1.0f / l0, inv1 = 1.0f / l1;
    #pragma unroll
    for (int nf = 0; nf < 8; nf++) {
        const int n = hoff + 8 * nf + 2 * tig;
        const float x0 = o_[nf][0] * inv0, y0 = o_[nf][1] * inv0;
        const float x1 = o_[nf][2] * inv1, y1 = o_[nf][3] * inv1;
        const size_t g0 = (tokbase + r0) * DMODEL + n;
        const size_t g1 = (tokbase + r1) * DMODEL + n;
        *(__nv_bfloat162*)&ohi[g0] = split_hi2(x0, y0);
        *(__nv_bfloat162*)&olo[g0] = split_lo2(x0, y0);
        *(__nv_bfloat162*)&ohi[g1] = split_hi2(x1, y1);
        *(__nv_bfloat162*)&olo[g1] = split_lo2(x1, y1);
    }
}

// ---------------------------------------------------------------------------
extern "C" void kernel_launch(void* const* d_in, const int* in_sizes, int n_in,
                              void* d_out, int out_size)
{
    const float* input = (const float*)d_in[0];
    // d_in[1] = mask (causal, hardcoded — ignored)
    const float* W_qkv = (const float*)d_in[2];
    const float* b_qkv = (const float*)d_in[3];
    const float* W_out = (const float*)d_in[4];
    const float* b_out = (const float*)d_in[5];
    float* out = (float*)d_out;

    __nv_bfloat16 *ahi, *alo, *bhi, *blo;
    __half *qh, *kh, *vh;
    cudaGetSymbolAddress((void**)&ahi, g_Ahi);
    cudaGetSymbolAddress((void**)&alo, g_Alo);
    cudaGetSymbolAddress((void**)&bhi, g_Bhi);
    cudaGetSymbolAddress((void**)&blo, g_Blo);
    cudaGetSymbolAddress((void**)&qh,  g_qh);
    cudaGetSymbolAddress((void**)&kh,  g_kh);
    cudaGetSymbolAddress((void**)&vh,  g_vh);

    float* kv_out = out + OUT_ELEMS;   // (out, k, v) layout

    cudaFuncSetAttribute(gemm_mma, cudaFuncAttributeMaxDynamicSharedMemorySize, GM_SMEM);
    cudaFuncSetAttribute(flash_mma, cudaFuncAttributeMaxDynamicSharedMemorySize, FL_SMEM);

    // 1) split input + W_qkv^T to bf16 hi/lo
    convert_hi_lo<<<(OUT_ELEMS / 4 + 255) / 256, 256>>>(input, ahi, alo, OUT_ELEMS / 4);
    convert_wt<<<dim3(NQKV / 32, DMODEL / 32), dim3(32, 8)>>>(W_qkv, bhi, blo, NQKV);

    // 2) QKV gemm -> q/k/v fp16, k/v fp32 to output
    gemm_mma<<<dim3(NQKV / 128, MROWS / 128), 256, GM_SMEM>>>(
        ahi, alo, bhi, blo, b_qkv, nullptr, NQKV, kv_out, qh, kh, vh);

    // 3) causal flash attention (tensor cores); writes att hi/lo in place of A
    flash_mma<<<dim3(SEQ / 128, NHEAD, BATCH), 256, FL_SMEM>>>(
        qh, kh, vh, ahi, alo);

    // 4) out = att @ W_out + b_out
    convert_wt<<<dim3(DMODEL / 32, DMODEL / 32), dim3(32, 8)>>>(W_out, bhi, blo, DMODEL);
    gemm_mma<<<dim3(DMODEL / 128, MROWS / 128), 256, GM_SMEM>>>(
        ahi, alo, bhi, blo, b_out, out, DMODEL, nullptr,
        nullptr, nullptr, nullptr);
}

// round 16
// speedup vs baseline: 1.7517x; 1.1260x over previous
#include <cuda_runtime.h>
#include <cuda_bf16.h>
#include <cuda_fp16.h>
#include <cstddef>
#include <cstdint>

// Problem constants
#define BATCH 2
#define SEQ   2048
#define DMODEL 1024
#define NHEAD 16
#define DHEAD 64
#define MROWS (BATCH * SEQ)          // 4096
#define NQKV  (3 * NHEAD * DHEAD)    // 3072
#define OUT_ELEMS (MROWS * DMODEL)   // 4194304

// Scratch (device globals — no allocation allowed)
__device__ __align__(16) __nv_bfloat16 g_Ahi[(size_t)MROWS * DMODEL];
__device__ __align__(16) __nv_bfloat16 g_Alo[(size_t)MROWS * DMODEL];
__device__ __align__(16) __nv_bfloat16 g_Bhi[(size_t)NQKV * DMODEL];   // [N,K] transposed
__device__ __align__(16) __nv_bfloat16 g_Blo[(size_t)NQKV * DMODEL];
__device__ __align__(16) __half        g_qh [(size_t)MROWS * DMODEL];
__device__ __align__(16) __half        g_kh [(size_t)MROWS * DMODEL];
__device__ __align__(16) __half        g_vh [(size_t)MROWS * DMODEL];
__device__ __align__(16) __half        g_ah [(size_t)MROWS * DMODEL];  // att (f16)
__device__ __align__(16) __half        g_wh [(size_t)DMODEL * DMODEL]; // W_out^T (f16)

// ---------------------------------------------------------------------------
// Baseline-PTX helpers (sm_103 target — NO arch-specific 'a' features)
// ---------------------------------------------------------------------------
__device__ __forceinline__ uint32_t smem_u32(const void* p) {
    uint32_t a;
    asm("{ .reg .u64 t; cvta.to.shared.u64 t, %1; cvt.u32.u64 %0, t; }"
        : "=r"(a) : "l"(p));
    return a;
}
#define CPASYNC16(dst, src) \
    asm volatile("cp.async.cg.shared.global [%0], [%1], 16;" :: "r"(dst), "l"(src))
#define CPCOMMIT() asm volatile("cp.async.commit_group;" ::: "memory")

__device__ __forceinline__ void ldx4(uint32_t* r, uint32_t addr) {
    asm volatile("ldmatrix.sync.aligned.m8n8.x4.shared.b16 {%0,%1,%2,%3}, [%4];"
                 : "=r"(r[0]), "=r"(r[1]), "=r"(r[2]), "=r"(r[3]) : "r"(addr));
}
__device__ __forceinline__ void ldx4t(uint32_t* r, uint32_t addr) {
    asm volatile("ldmatrix.sync.aligned.m8n8.x4.trans.shared.b16 {%0,%1,%2,%3}, [%4];"
                 : "=r"(r[0]), "=r"(r[1]), "=r"(r[2]), "=r"(r[3]) : "r"(addr));
}
__device__ __forceinline__ void mma_bf16(float* c, const uint32_t* a,
                                         uint32_t b0, uint32_t b1) {
    asm volatile(
        "mma.sync.aligned.m16n8k16.row.col.f32.bf16.bf16.f32 "
        "{%0,%1,%2,%3}, {%4,%5,%6,%7}, {%8,%9}, {%0,%1,%2,%3};"
        : "+f"(c[0]), "+f"(c[1]), "+f"(c[2]), "+f"(c[3])
        : "r"(a[0]), "r"(a[1]), "r"(a[2]), "r"(a[3]), "r"(b0), "r"(b1));
}
__device__ __forceinline__ void mma_f16(float* c, const uint32_t* a,
                                        uint32_t b0, uint32_t b1) {
    asm volatile(
        "mma.sync.aligned.m16n8k16.row.col.f32.f16.f16.f32 "
        "{%0,%1,%2,%3}, {%4,%5,%6,%7}, {%8,%9}, {%0,%1,%2,%3};"
        : "+f"(c[0]), "+f"(c[1]), "+f"(c[2]), "+f"(c[3])
        : "r"(a[0]), "r"(a[1]), "r"(a[2]), "r"(a[3]), "r"(b0), "r"(b1));
}
// pack two f32 into f16x2: lo half = first arg
__device__ __forceinline__ uint32_t packh2(float lo, float hi) {
    uint32_t r;
    asm("cvt.rn.f16x2.f32 %0, %1, %2;" : "=r"(r) : "f"(hi), "f"(lo));
    return r;
}
__device__ __forceinline__ __nv_bfloat162 split_hi2(float x, float y) {
    return __halves2bfloat162(__float2bfloat16(x), __float2bfloat16(y));
}
__device__ __forceinline__ __nv_bfloat162 split_lo2(float x, float y) {
    __nv_bfloat16 hx = __float2bfloat16(x), hy = __float2bfloat16(y);
    return __halves2bfloat162(__float2bfloat16(x - __bfloat162float(hx)),
                              __float2bfloat16(y - __bfloat162float(hy)));
}

// ---------------------------------------------------------------------------
// fp32 -> bf16 hi/lo split (elementwise)
// ---------------------------------------------------------------------------
__global__ void convert_hi_lo(const float* __restrict__ in,
                              __nv_bfloat16* __restrict__ hi,
                              __nv_bfloat16* __restrict__ lo, int n4)
{
    int i = blockIdx.x * blockDim.x + threadIdx.x;
    if (i >= n4) return;
    float4 v = ((const float4*)in)[i];
    __nv_bfloat162* H = (__nv_bfloat162*)hi;
    __nv_bfloat162* L = (__nv_bfloat162*)lo;
    H[2 * i]     = split_hi2(v.x, v.y);
    H[2 * i + 1] = split_hi2(v.z, v.w);
    L[2 * i]     = split_lo2(v.x, v.y);
    L[2 * i + 1] = split_lo2(v.z, v.w);
}

// W [K=1024, N] -> Wt hi/lo [N, 1024], tiled transpose + split (bf16)
__global__ void convert_wt(const float* __restrict__ W,
                           __nv_bfloat16* __restrict__ hi,
                           __nv_bfloat16* __restrict__ lo, int N)
{
    __shared__ float t[32][33];
    const int nx = blockIdx.x * 32 + threadIdx.x;
    const int k0 = blockIdx.y * 32;
    #pragma unroll
    for (int j = 0; j < 4; j++)
        t[threadIdx.y + j * 8][threadIdx.x] = W[(size_t)(k0 + threadIdx.y + j * 8) * N + nx];
    __syncthreads();
    const int k = k0 + threadIdx.x;
    #pragma unroll
    for (int j = 0; j < 4; j++) {
        const int nrow = blockIdx.x * 32 + threadIdx.y + j * 8;
        float x = t[threadIdx.x][threadIdx.y + j * 8];
        __nv_bfloat16 h = __float2bfloat16(x);
        hi[(size_t)nrow * 1024 + k] = h;
        lo[(size_t)nrow * 1024 + k] = __float2bfloat16(x - __bfloat162float(h));
    }
}

// W [K=1024, N] -> Wt f16 [N, 1024], tiled transpose
__global__ void convert_wt_f16(const float* __restrict__ W,
                               __half* __restrict__ wt, int N)
{
    __shared__ float t[32][33];
    const int nx = blockIdx.x * 32 + threadIdx.x;
    const int k0 = blockIdx.y * 32;
    #pragma unroll
    for (int j = 0; j < 4; j++)
        t[threadIdx.y + j * 8][threadIdx.x] = W[(size_t)(k0 + threadIdx.y + j * 8) * N + nx];
    __syncthreads();
    const int k = k0 + threadIdx.x;
    #pragma unroll
    for (int j = 0; j < 4; j++) {
        const int nrow = blockIdx.x * 32 + threadIdx.y + j * 8;
        wt[(size_t)nrow * 1024 + k] = __float2half_rn(t[threadIdx.x][threadIdx.y + j * 8]);
    }
}

// ---------------------------------------------------------------------------
// mma.sync split-bf16 GEMM (QKV): 2-stage cp.async, 2 CTAs/SM.
// Emits q (x 0.125*log2e) / k / v as fp16, and k/v fp32 into kv_out.
// ---------------------------------------------------------------------------
#define GK       1024
#define GBK      32
#define GNC      (GK / GBK)          // 32
#define TILE_B   (128 * 80)          // 10240 B per tile
#define STAGE_B  (4 * TILE_B)        // 40960 B
#define GM_SMEM  (2 * STAGE_B)       // 81920 B  (x2 CTAs = 163840 < 228KB)

// q pre-scale: 1/sqrt(64) * log2(e)  (softmax done in base-2)
#define QSCALE   0.18033688011112042f

__global__ __launch_bounds__(256, 2)
void gemm_mma(const __nv_bfloat16* __restrict__ Ahi, const __nv_bfloat16* __restrict__ Alo,
              const __nv_bfloat16* __restrict__ Bhi, const __nv_bfloat16* __restrict__ Blo,
              const float* __restrict__ bias, float* __restrict__ kv_out,
              __half* __restrict__ qh, __half* __restrict__ kh,
              __half* __restrict__ vh)
{
    extern __shared__ __align__(128) char smg[];
    const uint32_t sb = smem_u32(smg);
    const int tid = threadIdx.x, wid = tid >> 5, lane = tid & 31;
    const int wm = wid & 1, wn = wid >> 1;           // 2 x 4 warp grid
    const int bm = blockIdx.y * 128, bn = blockIdx.x * 128;

    const __nv_bfloat16* srcp[4];
    srcp[0] = Ahi + (size_t)bm * GK;
    srcp[1] = Alo + (size_t)bm * GK;
    srcp[2] = Bhi + (size_t)bn * GK;
    srcp[3] = Blo + (size_t)bn * GK;

    auto load_stage = [&](int c, int s) {
        const int k0 = c * GBK;
        #pragma unroll
        for (int t = 0; t < 4; t++) {
            const uint32_t tb = sb + s * STAGE_B + t * TILE_B;
            const __nv_bfloat16* bp = srcp[t] + k0;
            #pragma unroll
            for (int i = 0; i < 2; i++) {
                const int idx = tid + i * 256;       // 0..511
                const int row = idx >> 2, q = idx & 3;
                CPASYNC16(tb + row * 80 + q * 16,
                          (const char*)(bp + (size_t)row * GK + q * 8));
            }
        }
        CPCOMMIT();
    };

    const int a_row = (lane & 15);
    const int a_kb  = ((lane >> 4) << 3) * 2;
    const int b_row = ((lane >> 4) << 3) + (lane & 7);
    const int b_kb  = (((lane >> 3) & 1) << 3) * 2;

    float acc[4][4][4];
    #pragma unroll
    for (int i = 0; i < 4; i++)
        #pragma unroll
        for (int j = 0; j < 4; j++)
            #pragma unroll
            for (int k = 0; k < 4; k++) acc[i][j][k] = 0.f;

    load_stage(0, 0);
    #pragma unroll 1
    for (int c = 0; c < GNC; c++) {
        const int s = c & 1;
        if (c + 1 < GNC) {
            load_stage(c + 1, s ^ 1);
            asm volatile("cp.async.wait_group 1;" ::: "memory");
        } else {
            asm volatile("cp.async.wait_group 0;" ::: "memory");
        }
        __syncthreads();

        const uint32_t st = sb + s * STAGE_B;
        #pragma unroll
        for (int ks = 0; ks < 2; ks++) {
            uint32_t ah[4][4], al[4][4], bh[2][4], bl[2][4];
            const uint32_t akb = ks * 32 + a_kb;
            const uint32_t bkb = ks * 32 + b_kb;
            #pragma unroll
            for (int mf = 0; mf < 4; mf++) {
                const uint32_t off = (uint32_t)(wm * 64 + mf * 16 + a_row) * 80 + akb;
                ldx4(ah[mf], st + 0 * TILE_B + off);
                ldx4(al[mf], st + 1 * TILE_B + off);
            }
            #pragma unroll
            for (int nf2 = 0; nf2 < 2; nf2++) {
                const uint32_t off = (uint32_t)(wn * 32 + nf2 * 16 + b_row) * 80 + bkb;
                ldx4(bh[nf2], st + 2 * TILE_B + off);
                ldx4(bl[nf2], st + 3 * TILE_B + off);
            }
            #pragma unroll
            for (int mf = 0; mf < 4; mf++)
                #pragma unroll
                for (int nf2 = 0; nf2 < 2; nf2++)
                    #pragma unroll
                    for (int j = 0; j < 2; j++) {
                        float* a4 = acc[mf][nf2 * 2 + j];
                        mma_bf16(a4, ah[mf], bh[nf2][2 * j], bh[nf2][2 * j + 1]);
                        mma_bf16(a4, al[mf], bh[nf2][2 * j], bh[nf2][2 * j + 1]);
                        mma_bf16(a4, ah[mf], bl[nf2][2 * j], bl[nf2][2 * j + 1]);
                    }
        }
        __syncthreads();
    }

    // Epilogue
    const int gid = lane >> 2, tig = lane & 3;
    #pragma unroll
    for (int mf = 0; mf < 4; mf++) {
        #pragma unroll
        for (int nf = 0; nf < 4; nf++) {
            const int n = bn + wn * 32 + nf * 8 + 2 * tig;
            const float bx = bias[n], by = bias[n + 1];
            #pragma unroll
            for (int h = 0; h < 2; h++) {
                const int row = bm + wm * 64 + mf * 16 + gid + h * 8;
                float2 cv;
                cv.x = acc[mf][nf][2 * h + 0] + bx;
                cv.y = acc[mf][nf][2 * h + 1] + by;
                if (n < 1024) {                      // q: scale (incl. log2e), fp16
                    *(__half2*)&qh[(size_t)row * DMODEL + n] =
                        __floats2half2_rn(cv.x * QSCALE, cv.y * QSCALE);
                } else if (n < 2048) {               // k: fp16 + fp32 out
                    const int nk = n - 1024;
                    *(__half2*)&kh[(size_t)row * DMODEL + nk] = __floats2half2_rn(cv.x, cv.y);
                    *(float2*)&kv_out[(size_t)row * DMODEL + nk] = cv;
                } else {                             // v: fp16 + fp32 out
                    const int nv = n - 2048;
                    *(__half2*)&vh[(size_t)row * DMODEL + nv] = __floats2half2_rn(cv.x, cv.y);
                    *(float2*)&kv_out[(size_t)OUT_ELEMS + (size_t)row * DMODEL + nv] = cv;
                }
            }
        }
    }
}

// ---------------------------------------------------------------------------
// Single-product f16 GEMM (out-proj): C = A(f16) @ Bt(f16)^T + bias, fp32 out.
// Same structure as gemm_mma but 2 operand tiles and 1 product.
// ---------------------------------------------------------------------------
#define S2STAGE_B (2 * TILE_B)       // 20480 B
#define G2_SMEM   (2 * S2STAGE_B)    // 40960 B

__global__ __launch_bounds__(256, 2)
void gemm_f16(const __half* __restrict__ A, const __half* __restrict__ Bt,
              const float* __restrict__ bias, float* __restrict__ C, int N)
{
    extern __shared__ __align__(128) char smg[];
    const uint32_t sb = smem_u32(smg);
    const int tid = threadIdx.x, wid = tid >> 5, lane = tid & 31;
    const int wm = wid & 1, wn = wid >> 1;
    const int bm = blockIdx.y * 128, bn = blockIdx.x * 128;

    const __half* srcp[2];
    srcp[0] = A  + (size_t)bm * GK;
    srcp[1] = Bt + (size_t)bn * GK;

    auto load_stage = [&](int c, int s) {
        const int k0 = c * GBK;
        #pragma unroll
        for (int t = 0; t < 2; t++) {
            const uint32_t tb = sb + s * S2STAGE_B + t * TILE_B;
            const __half* bp = srcp[t] + k0;
            #pragma unroll
            for (int i = 0; i < 2; i++) {
                const int idx = tid + i * 256;
                const int row = idx >> 2, q = idx & 3;
                CPASYNC16(tb + row * 80 + q * 16,
                          (const char*)(bp + (size_t)row * GK + q * 8));
            }
        }
        CPCOMMIT();
    };

    const int a_row = (lane & 15);
    const int a_kb  = ((lane >> 4) << 3) * 2;
    const int b_row = ((lane >> 4) << 3) + (lane & 7);
    const int b_kb  = (((lane >> 3) & 1) << 3) * 2;

    float acc[4][4][4];
    #pragma unroll
    for (int i = 0; i < 4; i++)
        #pragma unroll
        for (int j = 0; j < 4; j++)
            #pragma unroll
            for (int k = 0; k < 4; k++) acc[i][j][k] = 0.f;

    load_stage(0, 0);
    #pragma unroll 1
    for (int c = 0; c < GNC; c++) {
        const int s = c & 1;
        if (c + 1 < GNC) {
            load_stage(c + 1, s ^ 1);
            asm volatile("cp.async.wait_group 1;" ::: "memory");
        } else {
            asm volatile("cp.async.wait_group 0;" ::: "memory");
        }
        __syncthreads();

        const uint32_t st = sb + s * S2STAGE_B;
        #pragma unroll
        for (int ks = 0; ks < 2; ks++) {
            uint32_t ah[4][4], bh[2][4];
            const uint32_t akb = ks * 32 + a_kb;
            const uint32_t bkb = ks * 32 + b_kb;
            #pragma unroll
            for (int mf = 0; mf < 4; mf++)
                ldx4(ah[mf], st + (uint32_t)(wm * 64 + mf * 16 + a_row) * 80 + akb);
            #pragma unroll
            for (int nf2 = 0; nf2 < 2; nf2++)
                ldx4(bh[nf2], st + TILE_B +
                     (uint32_t)(wn * 32 + nf2 * 16 + b_row) * 80 + bkb);
            #pragma unroll
            for (int mf = 0; mf < 4; mf++)
                #pragma unroll
                for (int nf2 = 0; nf2 < 2; nf2++)
                    #pragma unroll
                    for (int j = 0; j < 2; j++)
                        mma_f16(acc[mf][nf2 * 2 + j], ah[mf],
                                bh[nf2][2 * j], bh[nf2][2 * j + 1]);
        }
        __syncthreads();
    }

    const int gid = lane >> 2, tig = lane & 3;
    #pragma unroll
    for (int mf = 0; mf < 4; mf++) {
        #pragma unroll
        for (int nf = 0; nf < 4; nf++) {
            const int n = bn + wn * 32 + nf * 8 + 2 * tig;
            const float bx = bias[n], by = bias[n + 1];
            #pragma unroll
            for (int h = 0; h < 2; h++) {
                const int row = bm + wm * 64 + mf * 16 + gid + h * 8;
                float2 cv;
                cv.x = acc[mf][nf][2 * h + 0] + bx;
                cv.y = acc[mf][nf][2 * h + 1] + by;
                *(float2*)&C[(size_t)row * N + n] = cv;
            }
        }
    }
}

// ---------------------------------------------------------------------------
// Causal flash attention on mma.sync, all-fp16 operands, base-2 softmax.
// Output written as f16 (feeds single-product out-proj GEMM).
// ---------------------------------------------------------------------------
#define FQ0    0
#define FSTG   (128 * 144)           // 18432
#define FKH    0
#define FV     9216
#define FSTGB  18432
#define FL_SMEM (FSTG + 2 * FSTGB)   // 55296  (x2 CTAs = 110592 < 228KB)

__global__ __launch_bounds__(256, 2)
void flash_mma(const __half* __restrict__ qh, const __half* __restrict__ kh,
               const __half* __restrict__ vh, __half* __restrict__ oh)
{
    extern __shared__ __align__(128) char smf[];
    const uint32_t sb = smem_u32(smf);
    const int tid = threadIdx.x, wid = tid >> 5, lane = tid & 31;
    const int qt = (int)gridDim.x - 1 - (int)blockIdx.x;   // long blocks first
    const int h = blockIdx.y, b = blockIdx.z;
    const int bq0 = qt * 128;
    const int nkv = 2 * (qt + 1);
    const size_t tokbase = (size_t)b * SEQ;
    const int hoff = h * DHEAD;

    // Q tile -> smem (128 rows x 64 f16, row stride 144 B)
    #pragma unroll
    for (int i = 0; i < 4; i++) {
        const int idx = tid + 256 * i;                 // 0..1023
        const int row = idx >> 3, q = idx & 7;
        const size_t g = (tokbase + bq0 + row) * DMODEL + hoff + q * 8;
        CPASYNC16(sb + FQ0 + row * 144 + q * 16, (const char*)(qh + g));
    }

    auto load_kv = [&](int c, int s) {
        const size_t rb = tokbase + c * 64;
        const uint32_t st = sb + FSTG + s * FSTGB;
        #pragma unroll
        for (int i = 0; i < 2; i++) {
            const int idx = tid + 256 * i;             // 0..511
            const int row = idx >> 3, q = idx & 7;
            const size_t g = (rb + row) * DMODEL + hoff + q * 8;
            CPASYNC16(st + FKH + row * 144 + q * 16, (const char*)(kh + g));
            CPASYNC16(st + FV  + row * 144 + q * 16, (const char*)(vh + g));
        }
        CPCOMMIT();
    };
    load_kv(0, 0);   // group 0 = Q + kv stage 0

    const int a_row = (lane & 15);
    const int a_kb  = ((lane >> 4) << 3) * 2;
    const int b_row = ((lane >> 4) << 3) + (lane & 7);
    const int b_kb  = (((lane >> 3) & 1) << 3) * 2;
    const int gid = lane >> 2, tig = lane & 3;

    const int wrow0 = bq0 + wid * 16;                  // warp min row
    const int r0 = wrow0 + gid, r1 = r0 + 8;           // this lane's rows

    uint32_t qh_[4][4];
    float o_[8][4];
    #pragma unroll
    for (int i = 0; i < 8; i++)
        #pragma unroll
        for (int j = 0; j < 4; j++) o_[i][j] = 0.f;
    float m0 = -1e30f, m1 = -1e30f, l0 = 0.f, l1 = 0.f;
    bool qloaded = false;

    #pragma unroll 1
    for (int c = 0; c < nkv; c++) {
        const int s = c & 1;
        if (c + 1 < nkv) {
            load_kv(c + 1, s ^ 1);
            asm volatile("cp.async.wait_group 1;" ::: "memory");
        } else {
            asm volatile("cp.async.wait_group 0;" ::: "memory");
        }
        __syncthreads();

        if (!qloaded) {
            qloaded = true;
            const uint32_t off = (uint32_t)(wid * 16 + a_row) * 144 + a_kb;
            #pragma unroll
            for (int kf = 0; kf < 4; kf++)
                ldx4(qh_[kf], sb + FQ0 + off + kf * 32);
        }

        const int kv0 = c * 64;
        if (kv0 <= wrow0 + 15) {                       // not fully masked for warp
            const uint32_t st = sb + FSTG + s * FSTGB;

            // S' = Q K^T (base-2 logits; single f16 product)
            float s_[8][4];
            #pragma unroll
            for (int i = 0; i < 8; i++)
                #pragma unroll
                for (int j = 0; j < 4; j++) s_[i][j] = 0.f;
            #pragma unroll
            for (int kf = 0; kf < 4; kf++) {
                #pragma unroll
                for (int nf2 = 0; nf2 < 4; nf2++) {
                    uint32_t bh[4];
                    const uint32_t off = (uint32_t)(nf2 * 16 + b_row) * 144 + b_kb + kf * 32;
                    ldx4(bh, st + FKH + off);
                    mma_f16(s_[nf2 * 2],     qh_[kf], bh[0], bh[1]);
                    mma_f16(s_[nf2 * 2 + 1], qh_[kf], bh[2], bh[3]);
                }
            }

            // causal mask (only near the diagonal)
            if (kv0 + 63 > wrow0) {
                #pragma unroll
                for (int nf = 0; nf < 8; nf++)
                    #pragma unroll
                    for (int e = 0; e < 2; e++) {
                        const int col = kv0 + 8 * nf + 2 * tig + e;
                        if (col > r0) s_[nf][e]     = -1e30f;
                        if (col > r1) s_[nf][2 + e] = -1e30f;
                    }
            }

            // online softmax in base-2 (quad-lane reductions)
            float mx0 = -1e30f, mx1 = -1e30f;
            #pragma unroll
            for (int nf = 0; nf < 8; nf++) {
                mx0 = fmaxf(mx0, fmaxf(s_[nf][0], s_[nf][1]));
                mx1 = fmaxf(mx1, fmaxf(s_[nf][2], s_[nf][3]));
            }
            mx0 = fmaxf(mx0, __shfl_xor_sync(0xffffffffu, mx0, 1));
            mx0 = fmaxf(mx0, __shfl_xor_sync(0xffffffffu, mx0, 2));
            mx1 = fmaxf(mx1, __shfl_xor_sync(0xffffffffu, mx1, 1));
            mx1 = fmaxf(mx1, __shfl_xor_sync(0xffffffffu, mx1, 2));
            const float mn0 = fmaxf(m0, mx0), mn1 = fmaxf(m1, mx1);
            const float sc0 = exp2f(m0 - mn0), sc1 = exp2f(m1 - mn1);
            float rs0 = 0.f, rs1 = 0.f;
            #pragma unroll
            for (int nf = 0; nf < 8; nf++) {
                s_[nf][0] = exp2f(s_[nf][0] - mn0); rs0 += s_[nf][0];
                s_[nf][1] = exp2f(s_[nf][1] - mn0); rs0 += s_[nf][1];
                s_[nf][2] = exp2f(s_[nf][2] - mn1); rs1 += s_[nf][2];
                s_[nf][3] = exp2f(s_[nf][3] - mn1); rs1 += s_[nf][3];
            }
            rs0 += __shfl_xor_sync(0xffffffffu, rs0, 1);
            rs0 += __shfl_xor_sync(0xffffffffu, rs0, 2);
            rs1 += __shfl_xor_sync(0xffffffffu, rs1, 1);
            rs1 += __shfl_xor_sync(0xffffffffu, rs1, 2);
            l0 = l0 * sc0 + rs0; m0 = mn0;
            l1 = l1 * sc1 + rs1; m1 = mn1;
            #pragma unroll
            for (int nf = 0; nf < 8; nf++) {
                o_[nf][0] *= sc0; o_[nf][1] *= sc0;
                o_[nf][2] *= sc1; o_[nf][3] *= sc1;
            }

            // O += P V  (P from regs, V^T via ldmatrix.trans)
            #pragma unroll
            for (int kg = 0; kg < 4; kg++) {
                uint32_t pa[4];
                pa[0] = packh2(s_[2 * kg][0],     s_[2 * kg][1]);
                pa[1] = packh2(s_[2 * kg][2],     s_[2 * kg][3]);
                pa[2] = packh2(s_[2 * kg + 1][0], s_[2 * kg + 1][1]);
                pa[3] = packh2(s_[2 * kg + 1][2], s_[2 * kg + 1][3]);
                #pragma unroll
                for (int nf2 = 0; nf2 < 4; nf2++) {
                    uint32_t bv[4];
                    const uint32_t voff = (uint32_t)(kg * 16 + (lane & 15)) * 144
                                        + (uint32_t)(nf2 * 16 + (lane >> 4) * 8) * 2;
                    ldx4t(bv, st + FV + voff);
                    mma_f16(o_[nf2 * 2],     pa, bv[0], bv[1]);
                    mma_f16(o_[nf2 * 2 + 1], pa, bv[2], bv[3]);
                }
            }
        }
        __syncthreads();
    }

    // normalize + store att as f16
    const float inv0 = 1.0f / l0, inv1 = 1.0f / l1;
    #pragma unroll
    for (int nf = 0; nf < 8; nf++) {
        const int n = hoff + 8 * nf + 2 * tig;
        *(__half2*)&oh[(tokbase + r0) * DMODEL + n] =
            __floats2half2_rn(o_[nf][0] * inv0, o_[nf][1] * inv0);
        *(__half2*)&oh[(tokbase + r1) * DMODEL + n] =
            __floats2half2_rn(o_[nf][2] * inv1, o_[nf][3] * inv1);
    }
}

// ---------------------------------------------------------------------------
extern "C" void kernel_launch(void* const* d_in, const int* in_sizes, int n_in,
                              void* d_out, int out_size)
{
    const float* input = (const float*)d_in[0];
    // d_in[1] = mask (causal, hardcoded — ignored)
    const float* W_qkv = (const float*)d_in[2];
    const float* b_qkv = (const float*)d_in[3];
    const float* W_out = (const float*)d_in[4];
    const float* b_out = (const float*)d_in[5];
    float* out = (float*)d_out;

    __nv_bfloat16 *ahi, *alo, *bhi, *blo;
    __half *qh, *kh, *vh, *ah, *wh;
    cudaGetSymbolAddress((void**)&ahi, g_Ahi);
    cudaGetSymbolAddress((void**)&alo, g_Alo);
    cudaGetSymbolAddress((void**)&bhi, g_Bhi);
    cudaGetSymbolAddress((void**)&blo, g_Blo);
    cudaGetSymbolAddress((void**)&qh,  g_qh);
    cudaGetSymbolAddress((void**)&kh,  g_kh);
    cudaGetSymbolAddress((void**)&vh,  g_vh);
    cudaGetSymbolAddress((void**)&ah,  g_ah);
    cudaGetSymbolAddress((void**)&wh,  g_wh);

    float* kv_out = out + OUT_ELEMS;   // (out, k, v) layout

    cudaFuncSetAttribute(gemm_mma, cudaFuncAttributeMaxDynamicSharedMemorySize, GM_SMEM);
    cudaFuncSetAttribute(gemm_f16, cudaFuncAttributeMaxDynamicSharedMemorySize, G2_SMEM);
    cudaFuncSetAttribute(flash_mma, cudaFuncAttributeMaxDynamicSharedMemorySize, FL_SMEM);

    // 1) split input + W_qkv^T to bf16 hi/lo; W_out^T to f16
    convert_hi_lo<<<(OUT_ELEMS / 4 + 255) / 256, 256>>>(input, ahi, alo, OUT_ELEMS / 4);
    convert_wt<<<dim3(NQKV / 32, DMODEL / 32), dim3(32, 8)>>>(W_qkv, bhi, blo, NQKV);
    convert_wt_f16<<<dim3(DMODEL / 32, DMODEL / 32), dim3(32, 8)>>>(W_out, wh, DMODEL);

    // 2) QKV gemm -> q/k/v fp16, k/v fp32 to output
    gemm_mma<<<dim3(NQKV / 128, MROWS / 128), 256, GM_SMEM>>>(
        ahi, alo, bhi, blo, b_qkv, kv_out, qh, kh, vh);

    // 3) causal flash attention (tensor cores); att -> f16
    flash_mma<<<dim3(SEQ / 128, NHEAD, BATCH), 256, FL_SMEM>>>(
        qh, kh, vh, ah);

    // 4) out = att @ W_out + b_out  (single-product f16 GEMM)
    gemm_f16<<<dim3(DMODEL / 128, MROWS / 128), 256, G2_SMEM>>>(
        ah, wh, b_out, out, DMODEL);
}

// round 17
// speedup vs baseline: 1.9356x; 1.1050x over previous
#include <cuda_runtime.h>
#include <cuda_bf16.h>
#include <cuda_fp16.h>
#include <cstddef>
#include <cstdint>

// Problem constants
#define BATCH 2
#define SEQ   2048
#define DMODEL 1024
#define NHEAD 16
#define DHEAD 64
#define MROWS (BATCH * SEQ)          // 4096
#define NQKV  (3 * NHEAD * DHEAD)    // 3072
#define OUT_ELEMS (MROWS * DMODEL)   // 4194304

// Scratch (device globals — no allocation allowed)
__device__ __align__(16) __nv_bfloat16 g_Ahi[(size_t)MROWS * DMODEL];
__device__ __align__(16) __nv_bfloat16 g_Alo[(size_t)MROWS * DMODEL];
__device__ __align__(16) __nv_bfloat16 g_Bhi[(size_t)2048 * DMODEL];   // kv cols [N,K]
__device__ __align__(16) __nv_bfloat16 g_Blo[(size_t)2048 * DMODEL];
__device__ __align__(16) __half        g_ih [(size_t)MROWS * DMODEL];  // input (f16)
__device__ __align__(16) __half        g_wq [(size_t)DMODEL * DMODEL]; // Wq^T (f16)
__device__ __align__(16) __half        g_qh [(size_t)MROWS * DMODEL];
__device__ __align__(16) __half        g_kh [(size_t)MROWS * DMODEL];
__device__ __align__(16) __half        g_vh [(size_t)MROWS * DMODEL];
__device__ __align__(16) __half        g_ah [(size_t)MROWS * DMODEL];  // att (f16)
__device__ __align__(16) __half        g_wh [(size_t)DMODEL * DMODEL]; // W_out^T (f16)

// ---------------------------------------------------------------------------
// Baseline-PTX helpers (sm_103 target — NO arch-specific 'a' features)
// ---------------------------------------------------------------------------
__device__ __forceinline__ uint32_t smem_u32(const void* p) {
    uint32_t a;
    asm("{ .reg .u64 t; cvta.to.shared.u64 t, %1; cvt.u32.u64 %0, t; }"
        : "=r"(a) : "l"(p));
    return a;
}
#define CPASYNC16(dst, src) \
    asm volatile("cp.async.cg.shared.global [%0], [%1], 16;" :: "r"(dst), "l"(src))
#define CPCOMMIT() asm volatile("cp.async.commit_group;" ::: "memory")

__device__ __forceinline__ void ldx4(uint32_t* r, uint32_t addr) {
    asm volatile("ldmatrix.sync.aligned.m8n8.x4.shared.b16 {%0,%1,%2,%3}, [%4];"
                 : "=r"(r[0]), "=r"(r[1]), "=r"(r[2]), "=r"(r[3]) : "r"(addr));
}
__device__ __forceinline__ void ldx4t(uint32_t* r, uint32_t addr) {
    asm volatile("ldmatrix.sync.aligned.m8n8.x4.trans.shared.b16 {%0,%1,%2,%3}, [%4];"
                 : "=r"(r[0]), "=r"(r[1]), "=r"(r[2]), "=r"(r[3]) : "r"(addr));
}
__device__ __forceinline__ void mma_bf16(float* c, const uint32_t* a,
                                         uint32_t b0, uint32_t b1) {
    asm volatile(
        "mma.sync.aligned.m16n8k16.row.col.f32.bf16.bf16.f32 "
        "{%0,%1,%2,%3}, {%4,%5,%6,%7}, {%8,%9}, {%0,%1,%2,%3};"
        : "+f"(c[0]), "+f"(c[1]), "+f"(c[2]), "+f"(c[3])
        : "r"(a[0]), "r"(a[1]), "r"(a[2]), "r"(a[3]), "r"(b0), "r"(b1));
}
__device__ __forceinline__ void mma_f16(float* c, const uint32_t* a,
                                        uint32_t b0, uint32_t b1) {
    asm volatile(
        "mma.sync.aligned.m16n8k16.row.col.f32.f16.f16.f32 "
        "{%0,%1,%2,%3}, {%4,%5,%6,%7}, {%8,%9}, {%0,%1,%2,%3};"
        : "+f"(c[0]), "+f"(c[1]), "+f"(c[2]), "+f"(c[3])
        : "r"(a[0]), "r"(a[1]), "r"(a[2]), "r"(a[3]), "r"(b0), "r"(b1));
}
// pack two f32 into f16x2: lo half = first arg
__device__ __forceinline__ uint32_t packh2(float lo, float hi) {
    uint32_t r;
    asm("cvt.rn.f16x2.f32 %0, %1, %2;" : "=r"(r) : "f"(hi), "f"(lo));
    return r;
}
__device__ __forceinline__ __nv_bfloat162 split_hi2(float x, float y) {
    return __halves2bfloat162(__float2bfloat16(x), __float2bfloat16(y));
}
__device__ __forceinline__ __nv_bfloat162 split_lo2(float x, float y) {
    __nv_bfloat16 hx = __float2bfloat16(x), hy = __float2bfloat16(y);
    return __halves2bfloat162(__float2bfloat16(x - __bfloat162float(hx)),
                              __float2bfloat16(y - __bfloat162float(hy)));
}

// ---------------------------------------------------------------------------
// fp32 -> bf16 hi/lo split + f16 copy (elementwise)
// ---------------------------------------------------------------------------
__global__ void convert_hi_lo(const float* __restrict__ in,
                              __nv_bfloat16* __restrict__ hi,
                              __nv_bfloat16* __restrict__ lo,
                              __half* __restrict__ fh, int n4)
{
    int i = blockIdx.x * blockDim.x + threadIdx.x;
    if (i >= n4) return;
    float4 v = ((const float4*)in)[i];
    __nv_bfloat162* H = (__nv_bfloat162*)hi;
    __nv_bfloat162* L = (__nv_bfloat162*)lo;
    __half2* F = (__half2*)fh;
    H[2 * i]     = split_hi2(v.x, v.y);
    H[2 * i + 1] = split_hi2(v.z, v.w);
    L[2 * i]     = split_lo2(v.x, v.y);
    L[2 * i + 1] = split_lo2(v.z, v.w);
    F[2 * i]     = __floats2half2_rn(v.x, v.y);
    F[2 * i + 1] = __floats2half2_rn(v.z, v.w);
}

// W slice [K=1024, ncols] (row stride rs) -> Wt hi/lo [ncols, 1024] (bf16 split)
__global__ void convert_wt(const float* __restrict__ W,
                           __nv_bfloat16* __restrict__ hi,
                           __nv_bfloat16* __restrict__ lo, int rs)
{
    __shared__ float t[32][33];
    const int nx = blockIdx.x * 32 + threadIdx.x;
    const int k0 = blockIdx.y * 32;
    #pragma unroll
    for (int j = 0; j < 4; j++)
        t[threadIdx.y + j * 8][threadIdx.x] = W[(size_t)(k0 + threadIdx.y + j * 8) * rs + nx];
    __syncthreads();
    const int k = k0 + threadIdx.x;
    #pragma unroll
    for (int j = 0; j < 4; j++) {
        const int nrow = blockIdx.x * 32 + threadIdx.y + j * 8;
        float x = t[threadIdx.x][threadIdx.y + j * 8];
        __nv_bfloat16 h = __float2bfloat16(x);
        hi[(size_t)nrow * 1024 + k] = h;
        lo[(size_t)nrow * 1024 + k] = __float2bfloat16(x - __bfloat162float(h));
    }
}

// W slice [K=1024, ncols] (row stride rs) -> Wt f16 [ncols, 1024]
__global__ void convert_wt_f16(const float* __restrict__ W,
                               __half* __restrict__ wt, int rs)
{
    __shared__ float t[32][33];
    const int nx = blockIdx.x * 32 + threadIdx.x;
    const int k0 = blockIdx.y * 32;
    #pragma unroll
    for (int j = 0; j < 4; j++)
        t[threadIdx.y + j * 8][threadIdx.x] = W[(size_t)(k0 + threadIdx.y + j * 8) * rs + nx];
    __syncthreads();
    const int k = k0 + threadIdx.x;
    #pragma unroll
    for (int j = 0; j < 4; j++) {
        const int nrow = blockIdx.x * 32 + threadIdx.y + j * 8;
        wt[(size_t)nrow * 1024 + k] = __float2half_rn(t[threadIdx.x][threadIdx.y + j * 8]);
    }
}

// ---------------------------------------------------------------------------
// mma.sync split-bf16 GEMM (k/v columns only, N=2048): 2-stage cp.async,
// 2 CTAs/SM. Emits k / v as fp16 and fp32 into kv_out.
// ---------------------------------------------------------------------------
#define GK       1024
#define GBK      32
#define GNC      (GK / GBK)          // 32
#define TILE_B   (128 * 80)          // 10240 B per tile
#define STAGE_B  (4 * TILE_B)        // 40960 B
#define GM_SMEM  (2 * STAGE_B)       // 81920 B  (x2 CTAs = 163840 < 228KB)

// q pre-scale: 1/sqrt(64) * log2(e)  (softmax done in base-2)
#define QSCALE   0.18033688011112042f

__global__ __launch_bounds__(256, 2)
void gemm_mma(const __nv_bfloat16* __restrict__ Ahi, const __nv_bfloat16* __restrict__ Alo,
              const __nv_bfloat16* __restrict__ Bhi, const __nv_bfloat16* __restrict__ Blo,
              const float* __restrict__ bias, float* __restrict__ kv_out,
              __half* __restrict__ kh, __half* __restrict__ vh)
{
    extern __shared__ __align__(128) char smg[];
    const uint32_t sb = smem_u32(smg);
    const int tid = threadIdx.x, wid = tid >> 5, lane = tid & 31;
    const int wm = wid & 1, wn = wid >> 1;           // 2 x 4 warp grid
    const int bm = blockIdx.y * 128, bn = blockIdx.x * 128;

    const __nv_bfloat16* srcp[4];
    srcp[0] = Ahi + (size_t)bm * GK;
    srcp[1] = Alo + (size_t)bm * GK;
    srcp[2] = Bhi + (size_t)bn * GK;
    srcp[3] = Blo + (size_t)bn * GK;

    auto load_stage = [&](int c, int s) {
        const int k0 = c * GBK;
        #pragma unroll
        for (int t = 0; t < 4; t++) {
            const uint32_t tb = sb + s * STAGE_B + t * TILE_B;
            const __nv_bfloat16* bp = srcp[t] + k0;
            #pragma unroll
            for (int i = 0; i < 2; i++) {
                const int idx = tid + i * 256;       // 0..511
                const int row = idx >> 2, q = idx & 3;
                CPASYNC16(tb + row * 80 + q * 16,
                          (const char*)(bp + (size_t)row * GK + q * 8));
            }
        }
        CPCOMMIT();
    };

    const int a_row = (lane & 15);
    const int a_kb  = ((lane >> 4) << 3) * 2;
    const int b_row = ((lane >> 4) << 3) + (lane & 7);
    const int b_kb  = (((lane >> 3) & 1) << 3) * 2;

    float acc[4][4][4];
    #pragma unroll
    for (int i = 0; i < 4; i++)
        #pragma unroll
        for (int j = 0; j < 4; j++)
            #pragma unroll
            for (int k = 0; k < 4; k++) acc[i][j][k] = 0.f;

    load_stage(0, 0);
    #pragma unroll 1
    for (int c = 0; c < GNC; c++) {
        const int s = c & 1;
        if (c + 1 < GNC) {
            load_stage(c + 1, s ^ 1);
            asm volatile("cp.async.wait_group 1;" ::: "memory");
        } else {
            asm volatile("cp.async.wait_group 0;" ::: "memory");
        }
        __syncthreads();

        const uint32_t st = sb + s * STAGE_B;
        #pragma unroll
        for (int ks = 0; ks < 2; ks++) {
            uint32_t ah[4][4], al[4][4], bh[2][4], bl[2][4];
            const uint32_t akb = ks * 32 + a_kb;
            const uint32_t bkb = ks * 32 + b_kb;
            #pragma unroll
            for (int mf = 0; mf < 4; mf++) {
                const uint32_t off = (uint32_t)(wm * 64 + mf * 16 + a_row) * 80 + akb;
                ldx4(ah[mf], st + 0 * TILE_B + off);
                ldx4(al[mf], st + 1 * TILE_B + off);
            }
            #pragma unroll
            for (int nf2 = 0; nf2 < 2; nf2++) {
                const uint32_t off = (uint32_t)(wn * 32 + nf2 * 16 + b_row) * 80 + bkb;
                ldx4(bh[nf2], st + 2 * TILE_B + off);
                ldx4(bl[nf2], st + 3 * TILE_B + off);
            }
            #pragma unroll
            for (int mf = 0; mf < 4; mf++)
                #pragma unroll
                for (int nf2 = 0; nf2 < 2; nf2++)
                    #pragma unroll
                    for (int j = 0; j < 2; j++) {
                        float* a4 = acc[mf][nf2 * 2 + j];
                        mma_bf16(a4, ah[mf], bh[nf2][2 * j], bh[nf2][2 * j + 1]);
                        mma_bf16(a4, al[mf], bh[nf2][2 * j], bh[nf2][2 * j + 1]);
                        mma_bf16(a4, ah[mf], bl[nf2][2 * j], bl[nf2][2 * j + 1]);
                    }
        }
        __syncthreads();
    }

    // Epilogue: n in [0,2048): k cols then v cols
    const int gid = lane >> 2, tig = lane & 3;
    #pragma unroll
    for (int mf = 0; mf < 4; mf++) {
        #pragma unroll
        for (int nf = 0; nf < 4; nf++) {
            const int n = bn + wn * 32 + nf * 8 + 2 * tig;
            const float bx = bias[n], by = bias[n + 1];
            #pragma unroll
            for (int h = 0; h < 2; h++) {
                const int row = bm + wm * 64 + mf * 16 + gid + h * 8;
                float2 cv;
                cv.x = acc[mf][nf][2 * h + 0] + bx;
                cv.y = acc[mf][nf][2 * h + 1] + by;
                if (n < 1024) {                      // k: fp16 + fp32 out
                    *(__half2*)&kh[(size_t)row * DMODEL + n] = __floats2half2_rn(cv.x, cv.y);
                    *(float2*)&kv_out[(size_t)row * DMODEL + n] = cv;
                } else {                             // v: fp16 + fp32 out
                    const int nv = n - 1024;
                    *(__half2*)&vh[(size_t)row * DMODEL + nv] = __floats2half2_rn(cv.x, cv.y);
                    *(float2*)&kv_out[(size_t)OUT_ELEMS + (size_t)row * DMODEL + nv] = cv;
                }
            }
        }
    }
}

// ---------------------------------------------------------------------------
// Single-product f16 GEMM: C = A(f16) @ Bt(f16)^T + bias.
// qout == null: write fp32 C.  qout != null: write f16 q scaled by QSCALE.
// ---------------------------------------------------------------------------
#define S2STAGE_B (2 * TILE_B)       // 20480 B
#define G2_SMEM   (2 * S2STAGE_B)    // 40960 B

__global__ __launch_bounds__(256, 2)
void gemm_f16(const __half* __restrict__ A, const __half* __restrict__ Bt,
              const float* __restrict__ bias, float* __restrict__ C, int N,
              __half* __restrict__ qout)
{
    extern __shared__ __align__(128) char smg[];
    const uint32_t sb = smem_u32(smg);
    const int tid = threadIdx.x, wid = tid >> 5, lane = tid & 31;
    const int wm = wid & 1, wn = wid >> 1;
    const int bm = blockIdx.y * 128, bn = blockIdx.x * 128;

    const __half* srcp[2];
    srcp[0] = A  + (size_t)bm * GK;
    srcp[1] = Bt + (size_t)bn * GK;

    auto load_stage = [&](int c, int s) {
        const int k0 = c * GBK;
        #pragma unroll
        for (int t = 0; t < 2; t++) {
            const uint32_t tb = sb + s * S2STAGE_B + t * TILE_B;
            const __half* bp = srcp[t] + k0;
            #pragma unroll
            for (int i = 0; i < 2; i++) {
                const int idx = tid + i * 256;
                const int row = idx >> 2, q = idx & 3;
                CPASYNC16(tb + row * 80 + q * 16,
                          (const char*)(bp + (size_t)row * GK + q * 8));
            }
        }
        CPCOMMIT();
    };

    const int a_row = (lane & 15);
    const int a_kb  = ((lane >> 4) << 3) * 2;
    const int b_row = ((lane >> 4) << 3) + (lane & 7);
    const int b_kb  = (((lane >> 3) & 1) << 3) * 2;

    float acc[4][4][4];
    #pragma unroll
    for (int i = 0; i < 4; i++)
        #pragma unroll
        for (int j = 0; j < 4; j++)
            #pragma unroll
            for (int k = 0; k < 4; k++) acc[i][j][k] = 0.f;

    load_stage(0, 0);
    #pragma unroll 1
    for (int c = 0; c < GNC; c++) {
        const int s = c & 1;
        if (c + 1 < GNC) {
            load_stage(c + 1, s ^ 1);
            asm volatile("cp.async.wait_group 1;" ::: "memory");
        } else {
            asm volatile("cp.async.wait_group 0;" ::: "memory");
        }
        __syncthreads();

        const uint32_t st = sb + s * S2STAGE_B;
        #pragma unroll
        for (int ks = 0; ks < 2; ks++) {
            uint32_t ah[4][4], bh[2][4];
            const uint32_t akb = ks * 32 + a_kb;
            const uint32_t bkb = ks * 32 + b_kb;
            #pragma unroll
            for (int mf = 0; mf < 4; mf++)
                ldx4(ah[mf], st + (uint32_t)(wm * 64 + mf * 16 + a_row) * 80 + akb);
            #pragma unroll
            for (int nf2 = 0; nf2 < 2; nf2++)
                ldx4(bh[nf2], st + TILE_B +
                     (uint32_t)(wn * 32 + nf2 * 16 + b_row) * 80 + bkb);
            #pragma unroll
            for (int mf = 0; mf < 4; mf++)
                #pragma unroll
                for (int nf2 = 0; nf2 < 2; nf2++)
                    #pragma unroll
                    for (int j = 0; j < 2; j++)
                        mma_f16(acc[mf][nf2 * 2 + j], ah[mf],
                                bh[nf2][2 * j], bh[nf2][2 * j + 1]);
        }
        __syncthreads();
    }

    const int gid = lane >> 2, tig = lane & 3;
    #pragma unroll
    for (int mf = 0; mf < 4; mf++) {
        #pragma unroll
        for (int nf = 0; nf < 4; nf++) {
            const int n = bn + wn * 32 + nf * 8 + 2 * tig;
            const float bx = bias[n], by = bias[n + 1];
            #pragma unroll
            for (int h = 0; h < 2; h++) {
                const int row = bm + wm * 64 + mf * 16 + gid + h * 8;
                float2 cv;
                cv.x = acc[mf][nf][2 * h + 0] + bx;
                cv.y = acc[mf][nf][2 * h + 1] + by;
                if (qout) {
                    *(__half2*)&qout[(size_t)row * DMODEL + n] =
                        __floats2half2_rn(cv.x * QSCALE, cv.y * QSCALE);
                } else {
                    *(float2*)&C[(size_t)row * N + n] = cv;
                }
            }
        }
    }
}

// ---------------------------------------------------------------------------
// Causal flash attention on mma.sync, all-fp16 operands, base-2 softmax.
// Output written as f16 (feeds single-product out-proj GEMM).
// ---------------------------------------------------------------------------
#define FQ0    0
#define FSTG   (128 * 144)           // 18432
#define FKH    0
#define FV     9216
#define FSTGB  18432
#define FL_SMEM (FSTG + 2 * FSTGB)   // 55296  (x2 CTAs = 110592 < 228KB)

__global__ __launch_bounds__(256, 2)
void flash_mma(const __half* __restrict__ qh, const __half* __restrict__ kh,
               const __half* __restrict__ vh, __half* __restrict__ oh)
{
    extern __shared__ __align__(128) char smf[];
    const uint32_t sb = smem_u32(smf);
    const int tid = threadIdx.x, wid = tid >> 5, lane = tid & 31;
    const int qt = (int)gridDim.x - 1 - (int)blockIdx.x;   // long blocks first
    const int h = blockIdx.y, b = blockIdx.z;
    const int bq0 = qt * 128;
    const int nkv = 2 * (qt + 1);
    const size_t tokbase = (size_t)b * SEQ;
    const int hoff = h * DHEAD;

    // Q tile -> smem (128 rows x 64 f16, row stride 144 B)
    #pragma unroll
    for (int i = 0; i < 4; i++) {
        const int idx = tid + 256 * i;                 // 0..1023
        const int row = idx >> 3, q = idx & 7;
        const size_t g = (tokbase + bq0 + row) * DMODEL + hoff + q * 8;
        CPASYNC16(sb + FQ0 + row * 144 + q * 16, (const char*)(qh + g));
    }

    auto load_kv = [&](int c, int s) {
        const size_t rb = tokbase + c * 64;
        const uint32_t st = sb + FSTG + s * FSTGB;
        #pragma unroll
        for (int i = 0; i < 2; i++) {
            const int idx = tid + 256 * i;             // 0..511
            const int row = idx >> 3, q = idx & 7;
            const size_t g = (rb + row) * DMODEL + hoff + q * 8;
            CPASYNC16(st + FKH + row * 144 + q * 16, (const char*)(kh + g));
            CPASYNC16(st + FV  + row * 144 + q * 16, (const char*)(vh + g));
        }
        CPCOMMIT();
    };
    load_kv(0, 0);   // group 0 = Q + kv stage 0

    const int a_row = (lane & 15);
    const int a_kb  = ((lane >> 4) << 3) * 2;
    const int b_row = ((lane >> 4) << 3) + (lane & 7);
    const int b_kb  = (((lane >> 3) & 1) << 3) * 2;
    const int gid = lane >> 2, tig = lane & 3;

    const int wrow0 = bq0 + wid * 16;                  // warp min row
    const int r0 = wrow0 + gid, r1 = r0 + 8;           // this lane's rows

    uint32_t qh_[4][4];
    float o_[8][4];
    #pragma unroll
    for (int i = 0; i < 8; i++)
        #pragma unroll
        for (int j = 0; j < 4; j++) o_[i][j] = 0.f;
    float m0 = -1e30f, m1 = -1e30f, l0 = 0.f, l1 = 0.f;
    bool qloaded = false;

    #pragma unroll 1
    for (int c = 0; c < nkv; c++) {
        const int s = c & 1;
        if (c + 1 < nkv) {
            load_kv(c + 1, s ^ 1);
            asm volatile("cp.async.wait_group 1;" ::: "memory");
        } else {
            asm volatile("cp.async.wait_group 0;" ::: "memory");
        }
        __syncthreads();

        if (!qloaded) {
            qloaded = true;
            const uint32_t off = (uint32_t)(wid * 16 + a_row) * 144 + a_kb;
            #pragma unroll
            for (int kf = 0; kf < 4; kf++)
                ldx4(qh_[kf], sb + FQ0 + off + kf * 32);
        }

        const int kv0 = c * 64;
        if (kv0 <= wrow0 + 15) {                       // not fully masked for warp
            const uint32_t st = sb + FSTG + s * FSTGB;

            // S' = Q K^T (base-2 logits; single f16 product)
            float s_[8][4];
            #pragma unroll
            for (int i = 0; i < 8; i++)
                #pragma unroll
                for (int j = 0; j < 4; j++) s_[i][j] = 0.f;
            #pragma unroll
            for (int kf = 0; kf < 4; kf++) {
                #pragma unroll
                for (int nf2 = 0; nf2 < 4; nf2++) {
                    uint32_t bh[4];
                    const uint32_t off = (uint32_t)(nf2 * 16 + b_row) * 144 + b_kb + kf * 32;
                    ldx4(bh, st + FKH + off);
                    mma_f16(s_[nf2 * 2],     qh_[kf], bh[0], bh[1]);
                    mma_f16(s_[nf2 * 2 + 1], qh_[kf], bh[2], bh[3]);
                }
            }

            // causal mask (only near the diagonal)
            if (kv0 + 63 > wrow0) {
                #pragma unroll
                for (int nf = 0; nf < 8; nf++)
                    #pragma unroll
                    for (int e = 0; e < 2; e++) {
                        const int col = kv0 + 8 * nf + 2 * tig + e;
                        if (col > r0) s_[nf][e]     = -1e30f;
                        if (col > r1) s_[nf][2 + e] = -1e30f;
                    }
            }

            // online softmax in base-2 (quad-lane reductions)
            float mx0 = -1e30f, mx1 = -1e30f;
            #pragma unroll
            for (int nf = 0; nf < 8; nf++) {
                mx0 = fmaxf(mx0, fmaxf(s_[nf][0], s_[nf][1]));
                mx1 = fmaxf(mx1, fmaxf(s_[nf][2], s_[nf][3]));
            }
            mx0 = fmaxf(mx0, __shfl_xor_sync(0xffffffffu, mx0, 1));
            mx0 = fmaxf(mx0, __shfl_xor_sync(0xffffffffu, mx0, 2));
            mx1 = fmaxf(mx1, __shfl_xor_sync(0xffffffffu, mx1, 1));
            mx1 = fmaxf(mx1, __shfl_xor_sync(0xffffffffu, mx1, 2));
            const float mn0 = fmaxf(m0, mx0), mn1 = fmaxf(m1, mx1);
            const float sc0 = exp2f(m0 - mn0), sc1 = exp2f(m1 - mn1);
            float rs0 = 0.f, rs1 = 0.f;
            #pragma unroll
            for (int nf = 0; nf < 8; nf++) {
                s_[nf][0] = exp2f(s_[nf][0] - mn0); rs0 += s_[nf][0];
                s_[nf][1] = exp2f(s_[nf][1] - mn0); rs0 += s_[nf][1];
                s_[nf][2] = exp2f(s_[nf][2] - mn1); rs1 += s_[nf][2];
                s_[nf][3] = exp2f(s_[nf][3] - mn1); rs1 += s_[nf][3];
            }
            rs0 += __shfl_xor_sync(0xffffffffu, rs0, 1);
            rs0 += __shfl_xor_sync(0xffffffffu, rs0, 2);
            rs1 += __shfl_xor_sync(0xffffffffu, rs1, 1);
            rs1 += __shfl_xor_sync(0xffffffffu, rs1, 2);
            l0 = l0 * sc0 + rs0; m0 = mn0;
            l1 = l1 * sc1 + rs1; m1 = mn1;
            #pragma unroll
            for (int nf = 0; nf < 8; nf++) {
                o_[nf][0] *= sc0; o_[nf][1] *= sc0;
                o_[nf][2] *= sc1; o_[nf][3] *= sc1;
            }

            // O += P V  (P from regs, V^T via ldmatrix.trans)
            #pragma unroll
            for (int kg = 0; kg < 4; kg++) {
                uint32_t pa[4];
                pa[0] = packh2(s_[2 * kg][0],     s_[2 * kg][1]);
                pa[1] = packh2(s_[2 * kg][2],     s_[2 * kg][3]);
                pa[2] = packh2(s_[2 * kg + 1][0], s_[2 * kg + 1][1]);
                pa[3] = packh2(s_[2 * kg + 1][2], s_[2 * kg + 1][3]);
                #pragma unroll
                for (int nf2 = 0; nf2 < 4; nf2++) {
                    uint32_t bv[4];
                    const uint32_t voff = (uint32_t)(kg * 16 + (lane & 15)) * 144
                                        + (uint32_t)(nf2 * 16 + (lane >> 4) * 8) * 2;
                    ldx4t(bv, st + FV + voff);
                    mma_f16(o_[nf2 * 2],     pa, bv[0], bv[1]);
                    mma_f16(o_[nf2 * 2 + 1], pa, bv[2], bv[3]);
                }
            }
        }
        __syncthreads();
    }

    // normalize + store att as f16
    const float inv0 = 1.0f / l0, inv1 = 1.0f / l1;
    #pragma unroll
    for (int nf = 0; nf < 8; nf++) {
        const int n = hoff + 8 * nf + 2 * tig;
        *(__half2*)&oh[(tokbase + r0) * DMODEL + n] =
            __floats2half2_rn(o_[nf][0] * inv0, o_[nf][1] * inv0);
        *(__half2*)&oh[(tokbase + r1) * DMODEL + n] =
            __floats2half2_rn(o_[nf][2] * inv1, o_[nf][3] * inv1);
    }
}

// ---------------------------------------------------------------------------
extern "C" void kernel_launch(void* const* d_in, const int* in_sizes, int n_in,
                              void* d_out, int out_size)
{
    const float* input = (const float*)d_in[0];
    // d_in[1] = mask (causal, hardcoded — ignored)
    const float* W_qkv = (const float*)d_in[2];
    const float* b_qkv = (const float*)d_in[3];
    const float* W_out = (const float*)d_in[4];
    const float* b_out = (const float*)d_in[5];
    float* out = (float*)d_out;

    __nv_bfloat16 *ahi, *alo, *bhi, *blo;
    __half *ih, *wq, *qh, *kh, *vh, *ah, *wh;
    cudaGetSymbolAddress((void**)&ahi, g_Ahi);
    cudaGetSymbolAddress((void**)&alo, g_Alo);
    cudaGetSymbolAddress((void**)&bhi, g_Bhi);
    cudaGetSymbolAddress((void**)&blo, g_Blo);
    cudaGetSymbolAddress((void**)&ih,  g_ih);
    cudaGetSymbolAddress((void**)&wq,  g_wq);
    cudaGetSymbolAddress((void**)&qh,  g_qh);
    cudaGetSymbolAddress((void**)&kh,  g_kh);
    cudaGetSymbolAddress((void**)&vh,  g_vh);
    cudaGetSymbolAddress((void**)&ah,  g_ah);
    cudaGetSymbolAddress((void**)&wh,  g_wh);

    float* kv_out = out + OUT_ELEMS;   // (out, k, v) layout

    cudaFuncSetAttribute(gemm_mma, cudaFuncAttributeMaxDynamicSharedMemorySize, GM_SMEM);
    cudaFuncSetAttribute(gemm_f16, cudaFuncAttributeMaxDynamicSharedMemorySize, G2_SMEM);
    cudaFuncSetAttribute(flash_mma, cudaFuncAttributeMaxDynamicSharedMemorySize, FL_SMEM);

    // 1) converts: input -> bf16 hi/lo + f16; W_qkv q-cols -> f16 T;
    //    W_qkv kv-cols -> bf16 split T; W_out -> f16 T
    convert_hi_lo<<<(OUT_ELEMS / 4 + 255) / 256, 256>>>(input, ahi, alo, ih, OUT_ELEMS / 4);
    convert_wt_f16<<<dim3(1024 / 32, DMODEL / 32), dim3(32, 8)>>>(W_qkv, wq, NQKV);
    convert_wt<<<dim3(2048 / 32, DMODEL / 32), dim3(32, 8)>>>(W_qkv + 1024, bhi, blo, NQKV);
    convert_wt_f16<<<dim3(DMODEL / 32, DMODEL / 32), dim3(32, 8)>>>(W_out, wh, DMODEL);

    // 2a) q = input @ Wq + bq  (single-product f16, scaled to f16 q)
    gemm_f16<<<dim3(1024 / 128, MROWS / 128), 256, G2_SMEM>>>(
        ih, wq, b_qkv, nullptr, 1024, qh);

    // 2b) k/v gemm (split-bf16) -> k/v fp16 + fp32 outputs
    gemm_mma<<<dim3(2048 / 128, MROWS / 128), 256, GM_SMEM>>>(
        ahi, alo, bhi, blo, b_qkv + 1024, kv_out, kh, vh);

    // 3) causal flash attention (tensor cores); att -> f16
    flash_mma<<<dim3(SEQ / 128, NHEAD, BATCH), 256, FL_SMEM>>>(
        qh, kh, vh, ah);

    // 4) out = att @ W_out + b_out  (single-product f16 GEMM)
    gemm_f16<<<dim3(DMODEL / 128, MROWS / 128), 256, G2_SMEM>>>(
        ah, wh, b_out, out, DMODEL, nullptr);
}